// round 1
// baseline (speedup 1.0000x reference)
#include <cuda_runtime.h>
#include <math.h>

#define Nn 50000
#define E_MAX 1600000
#define F_IN 256
#define HCC 128
#define NHEAD 4
#define CDIM 32
#define NG 64
#define NCLS 16
#define SB 512
#define NB ((Nn + SB - 1) / SB)   // 98

// ---------------- scratch (device globals; no allocation allowed) ----------
__device__ float g_h[(size_t)Nn * HCC];     // GEMM output (per layer)
__device__ float g_o[(size_t)Nn * HCC];     // aggregation output (per layer)
__device__ float g_as[Nn * NHEAD];
__device__ float g_ad[Nn * NHEAD];
__device__ int   g_deg[Nn];
__device__ int   g_rowstart[Nn + 1];
__device__ int   g_cur[Nn];
__device__ int   g_csrc[E_MAX];
__device__ int   g_bsum[NB];
__device__ int   g_boff[NB];
__device__ float g_pool[NG * HCC];
__device__ int   g_cnt[NG];

// ---------------- init ----------------
__global__ void k_init() {
    int i = blockIdx.x * blockDim.x + threadIdx.x;
    if (i < Nn) g_deg[i] = 0;
    if (i < NG * HCC) g_pool[i] = 0.f;
    if (i < NG) g_cnt[i] = 0;
}

// ---------------- CSR build ----------------
__global__ void k_deg(const int* __restrict__ ei, int E) {
    int e = blockIdx.x * blockDim.x + threadIdx.x;
    if (e >= E) return;
    atomicAdd(&g_deg[ei[E + e]], 1);
}

__global__ void k_scan1() {
    __shared__ int s[SB];
    int t = threadIdx.x;
    int i = blockIdx.x * SB + t;
    s[t] = (i < Nn) ? g_deg[i] : 0;
    __syncthreads();
    for (int off = SB / 2; off; off >>= 1) {
        if (t < off) s[t] += s[t + off];
        __syncthreads();
    }
    if (t == 0) g_bsum[blockIdx.x] = s[0];
}

__global__ void k_scan2() {
    __shared__ int s[128];
    int t = threadIdx.x;
    int v = (t < NB) ? g_bsum[t] : 0;
    s[t] = v;
    __syncthreads();
    for (int off = 1; off < 128; off <<= 1) {
        int x = (t >= off) ? s[t - off] : 0;
        __syncthreads();
        s[t] += x;
        __syncthreads();
    }
    if (t < NB) g_boff[t] = s[t] - v;      // exclusive
    if (t == NB - 1) g_rowstart[Nn] = s[t];
}

__global__ void k_scan3() {
    __shared__ int s[SB];
    int t = threadIdx.x;
    int i = blockIdx.x * SB + t;
    int v = (i < Nn) ? g_deg[i] : 0;
    s[t] = v;
    __syncthreads();
    for (int off = 1; off < SB; off <<= 1) {
        int x = (t >= off) ? s[t - off] : 0;
        __syncthreads();
        s[t] += x;
        __syncthreads();
    }
    if (i < Nn) {
        int rs = g_boff[blockIdx.x] + s[t] - v;   // exclusive
        g_rowstart[i] = rs;
        g_cur[i] = rs;
    }
}

__global__ void k_scatter(const int* __restrict__ ei, int E) {
    int e = blockIdx.x * blockDim.x + threadIdx.x;
    if (e >= E) return;
    int d = ei[E + e];
    int pos = atomicAdd(&g_cur[d], 1);
    g_csrc[pos] = ei[e];
}

// ---------------- GEMM: C[M,128] = A[M,K] @ B[K,128] ----------------
// BM=64, BN=128, BK=16, 256 threads, each thread 4x8 outputs.
template <int K>
__global__ void k_gemm(const float* __restrict__ A, const float* __restrict__ B,
                       float* __restrict__ C) {
    __shared__ float As[16][64];
    __shared__ float Bs[16][128];
    int tid = threadIdx.x;
    int bm = blockIdx.x * 64;
    int ty = tid >> 4;          // 0..15
    int tx = tid & 15;          // 0..15
    int arow = tid >> 2;        // 0..63
    int ak = (tid & 3) * 4;
    int brow = tid >> 4;        // 0..15
    int bcol = (tid & 15) * 8;
    bool avalid = (bm + arow) < Nn;

    float acc[4][8];
#pragma unroll
    for (int i = 0; i < 4; i++)
#pragma unroll
        for (int j = 0; j < 8; j++) acc[i][j] = 0.f;

    for (int k0 = 0; k0 < K; k0 += 16) {
        float4 av = avalid ? *(const float4*)&A[(size_t)(bm + arow) * K + k0 + ak]
                           : make_float4(0.f, 0.f, 0.f, 0.f);
        As[ak + 0][arow] = av.x;
        As[ak + 1][arow] = av.y;
        As[ak + 2][arow] = av.z;
        As[ak + 3][arow] = av.w;
        float4 bv0 = *(const float4*)&B[(size_t)(k0 + brow) * HCC + bcol];
        float4 bv1 = *(const float4*)&B[(size_t)(k0 + brow) * HCC + bcol + 4];
        *(float4*)&Bs[brow][bcol] = bv0;
        *(float4*)&Bs[brow][bcol + 4] = bv1;
        __syncthreads();
#pragma unroll
        for (int kk = 0; kk < 16; kk++) {
            float4 a4 = *(const float4*)&As[kk][ty * 4];
            float4 b0 = *(const float4*)&Bs[kk][tx * 8];
            float4 b1 = *(const float4*)&Bs[kk][tx * 8 + 4];
            float a[4] = {a4.x, a4.y, a4.z, a4.w};
            float b[8] = {b0.x, b0.y, b0.z, b0.w, b1.x, b1.y, b1.z, b1.w};
#pragma unroll
            for (int i = 0; i < 4; i++)
#pragma unroll
                for (int j = 0; j < 8; j++) acc[i][j] = fmaf(a[i], b[j], acc[i][j]);
        }
        __syncthreads();
    }

#pragma unroll
    for (int i = 0; i < 4; i++) {
        int row = bm + ty * 4 + i;
        if (row < Nn) {
            float4 o0 = make_float4(acc[i][0], acc[i][1], acc[i][2], acc[i][3]);
            float4 o1 = make_float4(acc[i][4], acc[i][5], acc[i][6], acc[i][7]);
            *(float4*)&C[(size_t)row * HCC + tx * 8] = o0;
            *(float4*)&C[(size_t)row * HCC + tx * 8 + 4] = o1;
        }
    }
}

// ---------------- per-node attention coefficients ----------------
// one warp per node; lane owns 4 channels; heads are groups of 8 lanes.
__global__ void k_alpha(const float* __restrict__ h, const float* __restrict__ atts,
                        const float* __restrict__ attd) {
    int warp = (blockIdx.x * blockDim.x + threadIdx.x) >> 5;
    if (warp >= Nn) return;
    int lane = threadIdx.x & 31;
    float4 hv = *(const float4*)&h[(size_t)warp * HCC + lane * 4];
    float4 s4 = *(const float4*)&atts[lane * 4];
    float4 d4 = *(const float4*)&attd[lane * 4];
    float ps = hv.x * s4.x + hv.y * s4.y + hv.z * s4.z + hv.w * s4.w;
    float pd = hv.x * d4.x + hv.y * d4.y + hv.z * d4.z + hv.w * d4.w;
#pragma unroll
    for (int off = 4; off; off >>= 1) {
        ps += __shfl_down_sync(0xffffffffu, ps, off, 8);
        pd += __shfl_down_sync(0xffffffffu, pd, off, 8);
    }
    if ((lane & 7) == 0) {
        g_as[warp * 4 + (lane >> 3)] = ps;
        g_ad[warp * 4 + (lane >> 3)] = pd;
    }
}

__device__ __forceinline__ float leaky(float v) { return fmaxf(v, 0.2f * v); }

// ---------------- pull-style GAT aggregation (atomic-free) ----------------
// one warp per dst node. Two passes over its in-edges (max, then sum+agg).
// Self loop handled analytically. out = relu((sum p*h[src])/z + bias).
__global__ void k_aggregate(const float* __restrict__ h, const float* __restrict__ bias,
                            float* __restrict__ out) {
    int node = (blockIdx.x * blockDim.x + threadIdx.x) >> 5;
    if (node >= Nn) return;
    int lane = threadIdx.x & 31;
    int head = lane >> 3;

    float4 ad4 = *(const float4*)&g_ad[node * 4];
    float4 asl4 = *(const float4*)&g_as[node * 4];
    float adh[4] = {ad4.x, ad4.y, ad4.z, ad4.w};
    float ash[4] = {asl4.x, asl4.y, asl4.z, asl4.w};

    float m4[4];
#pragma unroll
    for (int hh = 0; hh < 4; hh++) m4[hh] = leaky(ash[hh] + adh[hh]);  // self loop

    int beg = g_rowstart[node];
    int end = g_rowstart[node + 1];

    // pass 1: per-head max over in-edges (lanes stride edges)
    for (int j = beg + lane; j < end; j += 32) {
        int s = g_csrc[j];
        float4 a4 = *(const float4*)&g_as[s * 4];
        float av[4] = {a4.x, a4.y, a4.z, a4.w};
#pragma unroll
        for (int hh = 0; hh < 4; hh++) m4[hh] = fmaxf(m4[hh], leaky(av[hh] + adh[hh]));
    }
#pragma unroll
    for (int off = 16; off; off >>= 1) {
#pragma unroll
        for (int hh = 0; hh < 4; hh++)
            m4[hh] = fmaxf(m4[hh], __shfl_xor_sync(0xffffffffu, m4[hh], off));
    }

    float m = m4[head];
    float ad = adh[head];

    // self-loop contribution
    float p_self = __expf(leaky(ash[head] + ad) - m);
    float z = p_self;
    float4 hv = *(const float4*)&h[(size_t)node * HCC + lane * 4];
    float4 acc;
    acc.x = p_self * hv.x;
    acc.y = p_self * hv.y;
    acc.z = p_self * hv.z;
    acc.w = p_self * hv.w;

    // pass 2: all lanes walk every edge; lane owns channels [lane*4, lane*4+4)
    for (int j0 = beg; j0 < end; j0 += 32) {
        int myj = j0 + lane;
        int sj = (myj < end) ? g_csrc[myj] : 0;
        int cnt = min(32, end - j0);
        for (int t = 0; t < cnt; t++) {
            int s = __shfl_sync(0xffffffffu, sj, t);
            float a = g_as[s * 4 + head];
            float p = __expf(leaky(a + ad) - m);
            z += p;
            float4 h2 = *(const float4*)&h[(size_t)s * HCC + lane * 4];
            acc.x = fmaf(p, h2.x, acc.x);
            acc.y = fmaf(p, h2.y, acc.y);
            acc.z = fmaf(p, h2.z, acc.z);
            acc.w = fmaf(p, h2.w, acc.w);
        }
    }

    float inv = 1.f / z;
    float4 b4 = *(const float4*)&bias[lane * 4];
    float4 o;
    o.x = fmaxf(fmaf(acc.x, inv, b4.x), 0.f);
    o.y = fmaxf(fmaf(acc.y, inv, b4.y), 0.f);
    o.z = fmaxf(fmaf(acc.z, inv, b4.z), 0.f);
    o.w = fmaxf(fmaf(acc.w, inv, b4.w), 0.f);
    *(float4*)&out[(size_t)node * HCC + lane * 4] = o;
}

// ---------------- pooling ----------------
__global__ void k_cnt(const int* __restrict__ batch) {
    __shared__ int sc[NG];
    int t = threadIdx.x;
    if (t < NG) sc[t] = 0;
    __syncthreads();
    int i = blockIdx.x * SB + t;
    if (i < Nn) atomicAdd(&sc[batch[i]], 1);
    __syncthreads();
    if (t < NG && sc[t]) atomicAdd(&g_cnt[t], sc[t]);
}

// 128 threads (one per channel), 64 contiguous nodes per block; batch sorted.
__global__ void k_pool(const float* __restrict__ hf, const int* __restrict__ batch) {
    int t = threadIdx.x;
    int n0 = blockIdx.x * 64;
    if (n0 >= Nn) return;
    int n1 = min(n0 + 64, Nn);
    int cur = batch[n0];
    float acc = 0.f;
    for (int n = n0; n < n1; n++) {
        int bb = batch[n];
        if (bb != cur) {
            atomicAdd(&g_pool[cur * HCC + t], acc);
            acc = 0.f;
            cur = bb;
        }
        acc += hf[(size_t)n * HCC + t];
    }
    atomicAdd(&g_pool[cur * HCC + t], acc);
}

// ---------------- classifier ----------------
__global__ void k_classifier(const float* __restrict__ Wc1, const float* __restrict__ bc1,
                             const float* __restrict__ Wc2, const float* __restrict__ bc2,
                             float* __restrict__ out) {
    int g = blockIdx.x;   // 64 graphs
    int t = threadIdx.x;  // 32 threads
    __shared__ float sg[HCC];
    __shared__ float sg1[CDIM];
    float inv = 1.f / (float)g_cnt[g];
    for (int c = t; c < HCC; c += 32) sg[c] = g_pool[g * HCC + c] * inv;
    __syncthreads();
    float a = bc1[t];
#pragma unroll 4
    for (int k = 0; k < HCC; k++) a = fmaf(sg[k], Wc1[k * CDIM + t], a);
    sg1[t] = a;
    __syncthreads();
    if (t < NCLS) {
        float b = bc2[t];
#pragma unroll
        for (int k = 0; k < CDIM; k++) b = fmaf(sg1[k], Wc2[k * NCLS + t], b);
        out[g * NCLS + t] = 1.f / (1.f + expf(-b));
    }
}

// ---------------- launch ----------------
extern "C" void kernel_launch(void* const* d_in, const int* in_sizes, int n_in,
                              void* d_out, int out_size) {
    const float* x    = (const float*)d_in[0];
    const int*   ei   = (const int*)d_in[1];
    const int*   batch= (const int*)d_in[2];
    const float* W1   = (const float*)d_in[3];
    const float* as1  = (const float*)d_in[4];
    const float* ad1  = (const float*)d_in[5];
    const float* b1   = (const float*)d_in[6];
    const float* W2   = (const float*)d_in[7];
    const float* as2  = (const float*)d_in[8];
    const float* ad2  = (const float*)d_in[9];
    const float* b2   = (const float*)d_in[10];
    const float* Wc1  = (const float*)d_in[11];
    const float* bc1  = (const float*)d_in[12];
    const float* Wc2  = (const float*)d_in[13];
    const float* bc2  = (const float*)d_in[14];
    float* out = (float*)d_out;

    int E = in_sizes[1] / 2;
    if (E > E_MAX) E = E_MAX;

    float *hP, *oP;
    cudaGetSymbolAddress((void**)&hP, g_h);
    cudaGetSymbolAddress((void**)&oP, g_o);

    int tpb = 256;
    int nodeWarpBlocks = (Nn * 32 + tpb - 1) / tpb;   // warp per node
    int gemmBlocks = (Nn + 63) / 64;

    k_init<<<(Nn + tpb - 1) / tpb, tpb>>>();
    k_deg<<<(E + tpb - 1) / tpb, tpb>>>(ei, E);
    k_scan1<<<NB, SB>>>();
    k_scan2<<<1, 128>>>();
    k_scan3<<<NB, SB>>>();
    k_scatter<<<(E + tpb - 1) / tpb, tpb>>>(ei, E);

    // layer 1
    k_gemm<F_IN><<<gemmBlocks, 256>>>(x, W1, hP);
    k_alpha<<<nodeWarpBlocks, tpb>>>(hP, as1, ad1);
    k_aggregate<<<nodeWarpBlocks, tpb>>>(hP, b1, oP);

    // layer 2
    k_gemm<HCC><<<gemmBlocks, 256>>>(oP, W2, hP);
    k_alpha<<<nodeWarpBlocks, tpb>>>(hP, as2, ad2);
    k_aggregate<<<nodeWarpBlocks, tpb>>>(hP, b2, oP);

    // pooling + classifier
    k_cnt<<<NB, SB>>>(batch);
    k_pool<<<(Nn + 63) / 64, HCC>>>(oP, batch);
    k_classifier<<<NG, 32>>>(Wc1, bc1, Wc2, bc2, out);
}

// round 2
// speedup vs baseline: 1.2473x; 1.2473x over previous
#include <cuda_runtime.h>
#include <cuda_bf16.h>
#include <math.h>

#define Nn 50000
#define E_MAX 1600000
#define F_IN 256
#define HCC 128
#define NHEAD 4
#define CDIM 32
#define NG 64
#define NCLS 16
#define SB 512
#define NB ((Nn + SB - 1) / SB)   // 98

// ---------------- scratch (device globals; no allocation allowed) ----------
__device__ float g_h[(size_t)Nn * HCC];     // GEMM output (per layer)
__device__ float g_o[(size_t)Nn * HCC];     // aggregation output (per layer)
__device__ float g_as[Nn * NHEAD];
__device__ float g_ad[Nn * NHEAD];
__device__ int   g_deg[Nn];
__device__ int   g_rowstart[Nn + 1];
__device__ int   g_cur[Nn];
__device__ int   g_csrc[E_MAX];
__device__ int   g_bsum[NB];
__device__ int   g_boff[NB];
__device__ float g_pool[NG * HCC];
__device__ int   g_cnt[NG];
// bf16x3 split scratch: A [M, 2K] = [hi | lo], BT [128, 2K] transposed = [hi | lo]
__device__ __nv_bfloat16 g_acat[(size_t)Nn * 2 * F_IN];      // 51.2 MB (layer2 uses prefix)
__device__ __nv_bfloat16 g_bcat[HCC * 2 * F_IN];             // 128 x 512

// ---------------- init ----------------
__global__ void k_init() {
    int i = blockIdx.x * blockDim.x + threadIdx.x;
    if (i < Nn) g_deg[i] = 0;
    if (i < NG * HCC) g_pool[i] = 0.f;
    if (i < NG) g_cnt[i] = 0;
}

// ---------------- CSR build ----------------
__global__ void k_deg(const int* __restrict__ ei, int E) {
    int e = blockIdx.x * blockDim.x + threadIdx.x;
    if (e >= E) return;
    atomicAdd(&g_deg[ei[E + e]], 1);
}

__global__ void k_scan1() {
    __shared__ int s[SB];
    int t = threadIdx.x;
    int i = blockIdx.x * SB + t;
    s[t] = (i < Nn) ? g_deg[i] : 0;
    __syncthreads();
    for (int off = SB / 2; off; off >>= 1) {
        if (t < off) s[t] += s[t + off];
        __syncthreads();
    }
    if (t == 0) g_bsum[blockIdx.x] = s[0];
}

__global__ void k_scan2() {
    __shared__ int s[128];
    int t = threadIdx.x;
    int v = (t < NB) ? g_bsum[t] : 0;
    s[t] = v;
    __syncthreads();
    for (int off = 1; off < 128; off <<= 1) {
        int x = (t >= off) ? s[t - off] : 0;
        __syncthreads();
        s[t] += x;
        __syncthreads();
    }
    if (t < NB) g_boff[t] = s[t] - v;      // exclusive
    if (t == NB - 1) g_rowstart[Nn] = s[t];
}

__global__ void k_scan3() {
    __shared__ int s[SB];
    int t = threadIdx.x;
    int i = blockIdx.x * SB + t;
    int v = (i < Nn) ? g_deg[i] : 0;
    s[t] = v;
    __syncthreads();
    for (int off = 1; off < SB; off <<= 1) {
        int x = (t >= off) ? s[t - off] : 0;
        __syncthreads();
        s[t] += x;
        __syncthreads();
    }
    if (i < Nn) {
        int rs = g_boff[blockIdx.x] + s[t] - v;   // exclusive
        g_rowstart[i] = rs;
        g_cur[i] = rs;
    }
}

__global__ void k_scatter(const int* __restrict__ ei, int E) {
    int e = blockIdx.x * blockDim.x + threadIdx.x;
    if (e >= E) return;
    int d = ei[E + e];
    int pos = atomicAdd(&g_cur[d], 1);
    g_csrc[pos] = ei[e];
}

// ---------------- bf16x3 split staging ----------------
// A [M,K] f32 -> g_acat [M,2K] bf16: cols [0,K)=hi, [K,2K)=lo
template <int K>
__global__ void k_splitA(const float* __restrict__ A, int M) {
    int idx = blockIdx.x * blockDim.x + threadIdx.x;   // over M*K/2 pairs
    if (idx >= M * (K / 2)) return;
    int r = idx / (K / 2);
    int c = (idx - r * (K / 2)) * 2;
    float2 v = *(const float2*)&A[(size_t)r * K + c];
    __nv_bfloat16 hx = __float2bfloat16(v.x);
    __nv_bfloat16 hy = __float2bfloat16(v.y);
    __nv_bfloat16 lx = __float2bfloat16(v.x - __bfloat162float(hx));
    __nv_bfloat16 ly = __float2bfloat16(v.y - __bfloat162float(hy));
    __nv_bfloat162* outh = (__nv_bfloat162*)&g_acat[(size_t)r * (2 * K) + c];
    __nv_bfloat162* outl = (__nv_bfloat162*)&g_acat[(size_t)r * (2 * K) + K + c];
    *outh = __nv_bfloat162(hx, hy);
    *outl = __nv_bfloat162(lx, ly);
}

// B [K,128] f32 -> g_bcat [128,2K] bf16 transposed: row n = [hi(B[:,n]) | lo(B[:,n])]
template <int K>
__global__ void k_splitB(const float* __restrict__ B) {
    int idx = blockIdx.x * blockDim.x + threadIdx.x;   // over K*128
    if (idx >= K * HCC) return;
    int k = idx / HCC;
    int n = idx - k * HCC;
    float v = B[idx];
    __nv_bfloat16 h = __float2bfloat16(v);
    __nv_bfloat16 l = __float2bfloat16(v - __bfloat162float(h));
    g_bcat[(size_t)n * (2 * K) + k] = h;
    g_bcat[(size_t)n * (2 * K) + K + k] = l;
}

// ---------------- tensor-core GEMM (bf16x3 == fp32-accurate) ----------------
// C[M,128] = A[M,K] x B[K,128] computed as K'=3K bf16 GEMM over split operands:
//   seg0 (kb<K):    Ahi x Bhi     seg1 (K<=kb<2K): Alo x Bhi    seg2: Ahi x Blo
// BM=128, BN=128, BK=64, 256 threads = 8 warps (4m x 2n), warp tile 32x64,
// mma.sync.m16n8k16.row.col.f32.bf16.bf16.f32. Smem row pad 72 -> conflict-free.
#define SA 72
template <int K>
__global__ void k_gemm_mma(float* __restrict__ C, int M) {
    __shared__ __nv_bfloat16 As[128 * SA];
    __shared__ __nv_bfloat16 Bs[128 * SA];
    const int tid = threadIdx.x;
    const int bm = blockIdx.x * 128;
    const int lane = tid & 31;
    const int warp = tid >> 5;
    const int wm = (warp & 3) * 32;      // warp m offset
    const int wn = (warp >> 2) * 64;     // warp n offset
    const int g = lane >> 2;             // group id 0..7
    const int t = lane & 3;              // thread in group

    float acc[2][8][4];
#pragma unroll
    for (int mt = 0; mt < 2; mt++)
#pragma unroll
        for (int nt = 0; nt < 8; nt++)
#pragma unroll
            for (int r = 0; r < 4; r++) acc[mt][nt][r] = 0.f;

    const int A2K = 2 * K;

    for (int kb = 0; kb < 3 * K; kb += 64) {
        int asrc = (kb < 2 * K) ? kb : kb - 2 * K;
        int bsrc = (kb < K) ? kb : kb - K;
        // load A tile: 128 rows x 64 cols bf16
#pragma unroll
        for (int i = 0; i < 4; i++) {
            int lin = tid + 256 * i;         // 0..1023
            int row = lin >> 3;
            int q = lin & 7;
            uint4 v = make_uint4(0u, 0u, 0u, 0u);
            if (bm + row < M)
                v = *(const uint4*)&g_acat[(size_t)(bm + row) * A2K + asrc + q * 8];
            *(uint4*)&As[row * SA + q * 8] = v;
        }
        // load B tile: 128 rows (n) x 64 cols (k) bf16
#pragma unroll
        for (int i = 0; i < 4; i++) {
            int lin = tid + 256 * i;
            int row = lin >> 3;
            int q = lin & 7;
            uint4 v = *(const uint4*)&g_bcat[(size_t)row * A2K + bsrc + q * 8];
            *(uint4*)&Bs[row * SA + q * 8] = v;
        }
        __syncthreads();

#pragma unroll
        for (int s = 0; s < 4; s++) {
            int k0 = s * 16;
            unsigned a[2][4], b[8][2];
#pragma unroll
            for (int mt = 0; mt < 2; mt++) {
                int r0 = wm + mt * 16 + g;
                a[mt][0] = *(const unsigned*)&As[r0 * SA + k0 + 2 * t];
                a[mt][1] = *(const unsigned*)&As[(r0 + 8) * SA + k0 + 2 * t];
                a[mt][2] = *(const unsigned*)&As[r0 * SA + k0 + 2 * t + 8];
                a[mt][3] = *(const unsigned*)&As[(r0 + 8) * SA + k0 + 2 * t + 8];
            }
#pragma unroll
            for (int nt = 0; nt < 8; nt++) {
                int n0 = wn + nt * 8 + g;
                b[nt][0] = *(const unsigned*)&Bs[n0 * SA + k0 + 2 * t];
                b[nt][1] = *(const unsigned*)&Bs[n0 * SA + k0 + 2 * t + 8];
            }
#pragma unroll
            for (int mt = 0; mt < 2; mt++)
#pragma unroll
                for (int nt = 0; nt < 8; nt++) {
                    asm volatile(
                        "mma.sync.aligned.m16n8k16.row.col.f32.bf16.bf16.f32 "
                        "{%0,%1,%2,%3}, {%4,%5,%6,%7}, {%8,%9}, {%0,%1,%2,%3};"
                        : "+f"(acc[mt][nt][0]), "+f"(acc[mt][nt][1]),
                          "+f"(acc[mt][nt][2]), "+f"(acc[mt][nt][3])
                        : "r"(a[mt][0]), "r"(a[mt][1]), "r"(a[mt][2]), "r"(a[mt][3]),
                          "r"(b[nt][0]), "r"(b[nt][1]));
                }
        }
        __syncthreads();
    }

    // epilogue
#pragma unroll
    for (int mt = 0; mt < 2; mt++) {
        int r0 = bm + wm + mt * 16 + g;
#pragma unroll
        for (int nt = 0; nt < 8; nt++) {
            int col = wn + nt * 8 + 2 * t;
            if (r0 < M)
                *(float2*)&C[(size_t)r0 * HCC + col] =
                    make_float2(acc[mt][nt][0], acc[mt][nt][1]);
            if (r0 + 8 < M)
                *(float2*)&C[(size_t)(r0 + 8) * HCC + col] =
                    make_float2(acc[mt][nt][2], acc[mt][nt][3]);
        }
    }
}

// ---------------- per-node attention coefficients ----------------
__global__ void k_alpha(const float* __restrict__ h, const float* __restrict__ atts,
                        const float* __restrict__ attd) {
    int warp = (blockIdx.x * blockDim.x + threadIdx.x) >> 5;
    if (warp >= Nn) return;
    int lane = threadIdx.x & 31;
    float4 hv = *(const float4*)&h[(size_t)warp * HCC + lane * 4];
    float4 s4 = *(const float4*)&atts[lane * 4];
    float4 d4 = *(const float4*)&attd[lane * 4];
    float ps = hv.x * s4.x + hv.y * s4.y + hv.z * s4.z + hv.w * s4.w;
    float pd = hv.x * d4.x + hv.y * d4.y + hv.z * d4.z + hv.w * d4.w;
#pragma unroll
    for (int off = 4; off; off >>= 1) {
        ps += __shfl_down_sync(0xffffffffu, ps, off, 8);
        pd += __shfl_down_sync(0xffffffffu, pd, off, 8);
    }
    if ((lane & 7) == 0) {
        g_as[warp * 4 + (lane >> 3)] = ps;
        g_ad[warp * 4 + (lane >> 3)] = pd;
    }
}

__device__ __forceinline__ float leaky(float v) { return fmaxf(v, 0.2f * v); }

// ---------------- pull-style GAT aggregation (atomic-free) ----------------
__global__ void k_aggregate(const float* __restrict__ h, const float* __restrict__ bias,
                            float* __restrict__ out) {
    int node = (blockIdx.x * blockDim.x + threadIdx.x) >> 5;
    if (node >= Nn) return;
    int lane = threadIdx.x & 31;
    int head = lane >> 3;

    float4 ad4 = *(const float4*)&g_ad[node * 4];
    float4 asl4 = *(const float4*)&g_as[node * 4];
    float adh[4] = {ad4.x, ad4.y, ad4.z, ad4.w};
    float ash[4] = {asl4.x, asl4.y, asl4.z, asl4.w};

    float m4[4];
#pragma unroll
    for (int hh = 0; hh < 4; hh++) m4[hh] = leaky(ash[hh] + adh[hh]);  // self loop

    int beg = g_rowstart[node];
    int end = g_rowstart[node + 1];

    for (int j = beg + lane; j < end; j += 32) {
        int s = g_csrc[j];
        float4 a4 = *(const float4*)&g_as[s * 4];
        float av[4] = {a4.x, a4.y, a4.z, a4.w};
#pragma unroll
        for (int hh = 0; hh < 4; hh++) m4[hh] = fmaxf(m4[hh], leaky(av[hh] + adh[hh]));
    }
#pragma unroll
    for (int off = 16; off; off >>= 1) {
#pragma unroll
        for (int hh = 0; hh < 4; hh++)
            m4[hh] = fmaxf(m4[hh], __shfl_xor_sync(0xffffffffu, m4[hh], off));
    }

    float m = m4[head];
    float ad = adh[head];

    float p_self = __expf(leaky(ash[head] + ad) - m);
    float z = p_self;
    float4 hv = *(const float4*)&h[(size_t)node * HCC + lane * 4];
    float4 acc;
    acc.x = p_self * hv.x;
    acc.y = p_self * hv.y;
    acc.z = p_self * hv.z;
    acc.w = p_self * hv.w;

    for (int j0 = beg; j0 < end; j0 += 32) {
        int myj = j0 + lane;
        int sj = (myj < end) ? g_csrc[myj] : 0;
        int cnt = min(32, end - j0);
        for (int t = 0; t < cnt; t++) {
            int s = __shfl_sync(0xffffffffu, sj, t);
            float a = g_as[s * 4 + head];
            float p = __expf(leaky(a + ad) - m);
            z += p;
            float4 h2 = *(const float4*)&h[(size_t)s * HCC + lane * 4];
            acc.x = fmaf(p, h2.x, acc.x);
            acc.y = fmaf(p, h2.y, acc.y);
            acc.z = fmaf(p, h2.z, acc.z);
            acc.w = fmaf(p, h2.w, acc.w);
        }
    }

    float inv = 1.f / z;
    float4 b4 = *(const float4*)&bias[lane * 4];
    float4 o;
    o.x = fmaxf(fmaf(acc.x, inv, b4.x), 0.f);
    o.y = fmaxf(fmaf(acc.y, inv, b4.y), 0.f);
    o.z = fmaxf(fmaf(acc.z, inv, b4.z), 0.f);
    o.w = fmaxf(fmaf(acc.w, inv, b4.w), 0.f);
    *(float4*)&out[(size_t)node * HCC + lane * 4] = o;
}

// ---------------- pooling ----------------
__global__ void k_cnt(const int* __restrict__ batch) {
    __shared__ int sc[NG];
    int t = threadIdx.x;
    if (t < NG) sc[t] = 0;
    __syncthreads();
    int i = blockIdx.x * SB + t;
    if (i < Nn) atomicAdd(&sc[batch[i]], 1);
    __syncthreads();
    if (t < NG && sc[t]) atomicAdd(&g_cnt[t], sc[t]);
}

__global__ void k_pool(const float* __restrict__ hf, const int* __restrict__ batch) {
    int t = threadIdx.x;
    int n0 = blockIdx.x * 64;
    if (n0 >= Nn) return;
    int n1 = min(n0 + 64, Nn);
    int cur = batch[n0];
    float acc = 0.f;
    for (int n = n0; n < n1; n++) {
        int bb = batch[n];
        if (bb != cur) {
            atomicAdd(&g_pool[cur * HCC + t], acc);
            acc = 0.f;
            cur = bb;
        }
        acc += hf[(size_t)n * HCC + t];
    }
    atomicAdd(&g_pool[cur * HCC + t], acc);
}

// ---------------- classifier ----------------
__global__ void k_classifier(const float* __restrict__ Wc1, const float* __restrict__ bc1,
                             const float* __restrict__ Wc2, const float* __restrict__ bc2,
                             float* __restrict__ out) {
    int g = blockIdx.x;
    int t = threadIdx.x;
    __shared__ float sg[HCC];
    __shared__ float sg1[CDIM];
    float inv = 1.f / (float)g_cnt[g];
    for (int c = t; c < HCC; c += 32) sg[c] = g_pool[g * HCC + c] * inv;
    __syncthreads();
    float a = bc1[t];
#pragma unroll 4
    for (int k = 0; k < HCC; k++) a = fmaf(sg[k], Wc1[k * CDIM + t], a);
    sg1[t] = a;
    __syncthreads();
    if (t < NCLS) {
        float b = bc2[t];
#pragma unroll
        for (int k = 0; k < CDIM; k++) b = fmaf(sg1[k], Wc2[k * NCLS + t], b);
        out[g * NCLS + t] = 1.f / (1.f + expf(-b));
    }
}

// ---------------- launch ----------------
extern "C" void kernel_launch(void* const* d_in, const int* in_sizes, int n_in,
                              void* d_out, int out_size) {
    const float* x    = (const float*)d_in[0];
    const int*   ei   = (const int*)d_in[1];
    const int*   batch= (const int*)d_in[2];
    const float* W1   = (const float*)d_in[3];
    const float* as1  = (const float*)d_in[4];
    const float* ad1  = (const float*)d_in[5];
    const float* b1   = (const float*)d_in[6];
    const float* W2   = (const float*)d_in[7];
    const float* as2  = (const float*)d_in[8];
    const float* ad2  = (const float*)d_in[9];
    const float* b2   = (const float*)d_in[10];
    const float* Wc1  = (const float*)d_in[11];
    const float* bc1  = (const float*)d_in[12];
    const float* Wc2  = (const float*)d_in[13];
    const float* bc2  = (const float*)d_in[14];
    float* out = (float*)d_out;

    int E = in_sizes[1] / 2;
    if (E > E_MAX) E = E_MAX;

    float *hP, *oP;
    cudaGetSymbolAddress((void**)&hP, g_h);
    cudaGetSymbolAddress((void**)&oP, g_o);

    int tpb = 256;
    int nodeWarpBlocks = (Nn * 32 + tpb - 1) / tpb;
    int mmaBlocks = (Nn + 127) / 128;   // 391

    k_init<<<(Nn + tpb - 1) / tpb, tpb>>>();
    k_deg<<<(E + tpb - 1) / tpb, tpb>>>(ei, E);
    k_scan1<<<NB, SB>>>();
    k_scan2<<<1, 128>>>();
    k_scan3<<<NB, SB>>>();
    k_scatter<<<(E + tpb - 1) / tpb, tpb>>>(ei, E);

    // layer 1: h = x @ W1 (bf16x3 tensor-core path)
    k_splitB<F_IN><<<(F_IN * HCC + tpb - 1) / tpb, tpb>>>(W1);
    k_splitA<F_IN><<<(Nn * (F_IN / 2) + tpb - 1) / tpb, tpb>>>(x, Nn);
    k_gemm_mma<F_IN><<<mmaBlocks, 256>>>(hP, Nn);
    k_alpha<<<nodeWarpBlocks, tpb>>>(hP, as1, ad1);
    k_aggregate<<<nodeWarpBlocks, tpb>>>(hP, b1, oP);

    // layer 2: h = o @ W2
    k_splitB<HCC><<<(HCC * HCC + tpb - 1) / tpb, tpb>>>(W2);
    k_splitA<HCC><<<(Nn * (HCC / 2) + tpb - 1) / tpb, tpb>>>(oP, Nn);
    k_gemm_mma<HCC><<<mmaBlocks, 256>>>(hP, Nn);
    k_alpha<<<nodeWarpBlocks, tpb>>>(hP, as2, ad2);
    k_aggregate<<<nodeWarpBlocks, tpb>>>(hP, b2, oP);

    // pooling + classifier
    k_cnt<<<NB, SB>>>(batch);
    k_pool<<<(Nn + 63) / 64, HCC>>>(oP, batch);
    k_classifier<<<NG, 32>>>(Wc1, bc1, Wc2, bc2, out);
}

// round 3
// speedup vs baseline: 1.4061x; 1.1274x over previous
#include <cuda_runtime.h>
#include <cuda_bf16.h>
#include <math.h>

#define Nn 50000
#define E_MAX 1600000
#define F_IN 256
#define HCC 128
#define NHEAD 4
#define CDIM 32
#define NG 64
#define NCLS 16
#define SB 512
#define NB ((Nn + SB - 1) / SB)   // 98

// ---------------- scratch (device globals; no allocation allowed) ----------
__device__ float g_h[(size_t)Nn * HCC];
__device__ float g_o[(size_t)Nn * HCC];
__device__ float g_as[Nn * NHEAD];
__device__ float g_ad[Nn * NHEAD];
__device__ int   g_deg[Nn];
__device__ int   g_rowstart[Nn + 1];
__device__ int   g_cur[Nn];
__device__ int   g_csrc[E_MAX];
__device__ int   g_bsum[NB];
__device__ int   g_boff[NB];
__device__ float g_pool[NG * HCC];
__device__ int   g_cnt[NG];
__device__ __nv_bfloat16 g_acat[(size_t)Nn * 2 * F_IN];
__device__ __nv_bfloat16 g_bcat[HCC * 2 * F_IN];

// ---------------- init ----------------
__global__ void k_init() {
    int i = blockIdx.x * blockDim.x + threadIdx.x;
    if (i < Nn) g_deg[i] = 0;
    if (i < NG * HCC) g_pool[i] = 0.f;
    if (i < NG) g_cnt[i] = 0;
}

// ---------------- CSR build (4 edges / thread, vectorized) ----------------
__global__ void k_deg(const int* __restrict__ ei, int E) {
    int e4 = (blockIdx.x * blockDim.x + threadIdx.x) * 4;
    if (e4 >= E) return;
    if (e4 + 3 < E && ((E & 3) == 0)) {
        int4 d = *(const int4*)&ei[E + e4];
        atomicAdd(&g_deg[d.x], 1);
        atomicAdd(&g_deg[d.y], 1);
        atomicAdd(&g_deg[d.z], 1);
        atomicAdd(&g_deg[d.w], 1);
    } else {
        for (int e = e4; e < min(e4 + 4, E); e++) atomicAdd(&g_deg[ei[E + e]], 1);
    }
}

__global__ void k_scan1() {
    __shared__ int s[SB];
    int t = threadIdx.x;
    int i = blockIdx.x * SB + t;
    s[t] = (i < Nn) ? g_deg[i] : 0;
    __syncthreads();
    for (int off = SB / 2; off; off >>= 1) {
        if (t < off) s[t] += s[t + off];
        __syncthreads();
    }
    if (t == 0) g_bsum[blockIdx.x] = s[0];
}

__global__ void k_scan2() {
    __shared__ int s[128];
    int t = threadIdx.x;
    int v = (t < NB) ? g_bsum[t] : 0;
    s[t] = v;
    __syncthreads();
    for (int off = 1; off < 128; off <<= 1) {
        int x = (t >= off) ? s[t - off] : 0;
        __syncthreads();
        s[t] += x;
        __syncthreads();
    }
    if (t < NB) g_boff[t] = s[t] - v;
    if (t == NB - 1) g_rowstart[Nn] = s[t];
}

__global__ void k_scan3() {
    __shared__ int s[SB];
    int t = threadIdx.x;
    int i = blockIdx.x * SB + t;
    int v = (i < Nn) ? g_deg[i] : 0;
    s[t] = v;
    __syncthreads();
    for (int off = 1; off < SB; off <<= 1) {
        int x = (t >= off) ? s[t - off] : 0;
        __syncthreads();
        s[t] += x;
        __syncthreads();
    }
    if (i < Nn) {
        int rs = g_boff[blockIdx.x] + s[t] - v;
        g_rowstart[i] = rs;
        g_cur[i] = rs;
    }
}

__global__ void k_scatter(const int* __restrict__ ei, int E) {
    int e4 = (blockIdx.x * blockDim.x + threadIdx.x) * 4;
    if (e4 >= E) return;
    if (e4 + 3 < E && ((E & 3) == 0)) {
        int4 s = *(const int4*)&ei[e4];
        int4 d = *(const int4*)&ei[E + e4];
        g_csrc[atomicAdd(&g_cur[d.x], 1)] = s.x;
        g_csrc[atomicAdd(&g_cur[d.y], 1)] = s.y;
        g_csrc[atomicAdd(&g_cur[d.z], 1)] = s.z;
        g_csrc[atomicAdd(&g_cur[d.w], 1)] = s.w;
    } else {
        for (int e = e4; e < min(e4 + 4, E); e++)
            g_csrc[atomicAdd(&g_cur[ei[E + e]], 1)] = ei[e];
    }
}

// ---------------- bf16x3 split staging ----------------
template <int K>
__global__ void k_splitA(const float* __restrict__ A, int M) {
    int idx = blockIdx.x * blockDim.x + threadIdx.x;
    if (idx >= M * (K / 2)) return;
    int r = idx / (K / 2);
    int c = (idx - r * (K / 2)) * 2;
    float2 v = *(const float2*)&A[(size_t)r * K + c];
    __nv_bfloat16 hx = __float2bfloat16(v.x);
    __nv_bfloat16 hy = __float2bfloat16(v.y);
    __nv_bfloat16 lx = __float2bfloat16(v.x - __bfloat162float(hx));
    __nv_bfloat16 ly = __float2bfloat16(v.y - __bfloat162float(hy));
    *(__nv_bfloat162*)&g_acat[(size_t)r * (2 * K) + c] = __nv_bfloat162(hx, hy);
    *(__nv_bfloat162*)&g_acat[(size_t)r * (2 * K) + K + c] = __nv_bfloat162(lx, ly);
}

template <int K>
__global__ void k_splitB(const float* __restrict__ B) {
    int idx = blockIdx.x * blockDim.x + threadIdx.x;
    if (idx >= K * HCC) return;
    int k = idx / HCC;
    int n = idx - k * HCC;
    float v = B[idx];
    __nv_bfloat16 h = __float2bfloat16(v);
    __nv_bfloat16 l = __float2bfloat16(v - __bfloat162float(h));
    g_bcat[(size_t)n * (2 * K) + k] = h;
    g_bcat[(size_t)n * (2 * K) + K + k] = l;
}

// ---------------- tensor-core GEMM (bf16x3) ----------------
#define SA 72
template <int K>
__global__ void k_gemm_mma(float* __restrict__ C, int M) {
    __shared__ __nv_bfloat16 As[128 * SA];
    __shared__ __nv_bfloat16 Bs[128 * SA];
    const int tid = threadIdx.x;
    const int bm = blockIdx.x * 128;
    const int lane = tid & 31;
    const int warp = tid >> 5;
    const int wm = (warp & 3) * 32;
    const int wn = (warp >> 2) * 64;
    const int g = lane >> 2;
    const int t = lane & 3;

    float acc[2][8][4];
#pragma unroll
    for (int mt = 0; mt < 2; mt++)
#pragma unroll
        for (int nt = 0; nt < 8; nt++)
#pragma unroll
            for (int r = 0; r < 4; r++) acc[mt][nt][r] = 0.f;

    const int A2K = 2 * K;

    for (int kb = 0; kb < 3 * K; kb += 64) {
        int asrc = (kb < 2 * K) ? kb : kb - 2 * K;
        int bsrc = (kb < K) ? kb : kb - K;
#pragma unroll
        for (int i = 0; i < 4; i++) {
            int lin = tid + 256 * i;
            int row = lin >> 3;
            int q = lin & 7;
            uint4 v = make_uint4(0u, 0u, 0u, 0u);
            if (bm + row < M)
                v = *(const uint4*)&g_acat[(size_t)(bm + row) * A2K + asrc + q * 8];
            *(uint4*)&As[row * SA + q * 8] = v;
        }
#pragma unroll
        for (int i = 0; i < 4; i++) {
            int lin = tid + 256 * i;
            int row = lin >> 3;
            int q = lin & 7;
            uint4 v = *(const uint4*)&g_bcat[(size_t)row * A2K + bsrc + q * 8];
            *(uint4*)&Bs[row * SA + q * 8] = v;
        }
        __syncthreads();

#pragma unroll
        for (int s = 0; s < 4; s++) {
            int k0 = s * 16;
            unsigned a[2][4], b[8][2];
#pragma unroll
            for (int mt = 0; mt < 2; mt++) {
                int r0 = wm + mt * 16 + g;
                a[mt][0] = *(const unsigned*)&As[r0 * SA + k0 + 2 * t];
                a[mt][1] = *(const unsigned*)&As[(r0 + 8) * SA + k0 + 2 * t];
                a[mt][2] = *(const unsigned*)&As[r0 * SA + k0 + 2 * t + 8];
                a[mt][3] = *(const unsigned*)&As[(r0 + 8) * SA + k0 + 2 * t + 8];
            }
#pragma unroll
            for (int nt = 0; nt < 8; nt++) {
                int n0 = wn + nt * 8 + g;
                b[nt][0] = *(const unsigned*)&Bs[n0 * SA + k0 + 2 * t];
                b[nt][1] = *(const unsigned*)&Bs[n0 * SA + k0 + 2 * t + 8];
            }
#pragma unroll
            for (int mt = 0; mt < 2; mt++)
#pragma unroll
                for (int nt = 0; nt < 8; nt++) {
                    asm volatile(
                        "mma.sync.aligned.m16n8k16.row.col.f32.bf16.bf16.f32 "
                        "{%0,%1,%2,%3}, {%4,%5,%6,%7}, {%8,%9}, {%0,%1,%2,%3};"
                        : "+f"(acc[mt][nt][0]), "+f"(acc[mt][nt][1]),
                          "+f"(acc[mt][nt][2]), "+f"(acc[mt][nt][3])
                        : "r"(a[mt][0]), "r"(a[mt][1]), "r"(a[mt][2]), "r"(a[mt][3]),
                          "r"(b[nt][0]), "r"(b[nt][1]));
                }
        }
        __syncthreads();
    }

#pragma unroll
    for (int mt = 0; mt < 2; mt++) {
        int r0 = bm + wm + mt * 16 + g;
#pragma unroll
        for (int nt = 0; nt < 8; nt++) {
            int col = wn + nt * 8 + 2 * t;
            if (r0 < M)
                *(float2*)&C[(size_t)r0 * HCC + col] =
                    make_float2(acc[mt][nt][0], acc[mt][nt][1]);
            if (r0 + 8 < M)
                *(float2*)&C[(size_t)(r0 + 8) * HCC + col] =
                    make_float2(acc[mt][nt][2], acc[mt][nt][3]);
        }
    }
}

// ---------------- per-node attention coefficients ----------------
__global__ void k_alpha(const float* __restrict__ h, const float* __restrict__ atts,
                        const float* __restrict__ attd) {
    int warp = (blockIdx.x * blockDim.x + threadIdx.x) >> 5;
    if (warp >= Nn) return;
    int lane = threadIdx.x & 31;
    float4 hv = *(const float4*)&h[(size_t)warp * HCC + lane * 4];
    float4 s4 = *(const float4*)&atts[lane * 4];
    float4 d4 = *(const float4*)&attd[lane * 4];
    float ps = hv.x * s4.x + hv.y * s4.y + hv.z * s4.z + hv.w * s4.w;
    float pd = hv.x * d4.x + hv.y * d4.y + hv.z * d4.z + hv.w * d4.w;
#pragma unroll
    for (int off = 4; off; off >>= 1) {
        ps += __shfl_down_sync(0xffffffffu, ps, off, 8);
        pd += __shfl_down_sync(0xffffffffu, pd, off, 8);
    }
    if ((lane & 7) == 0) {
        g_as[warp * 4 + (lane >> 3)] = ps;
        g_ad[warp * 4 + (lane >> 3)] = pd;
    }
}

__device__ __forceinline__ float leaky(float v) { return fmaxf(v, 0.2f * v); }

// ---------------- pull-style GAT aggregation (atomic-free, MLP-unrolled) ----
__global__ void k_aggregate(const float* __restrict__ h, const float* __restrict__ bias,
                            float* __restrict__ out) {
    int node = (blockIdx.x * blockDim.x + threadIdx.x) >> 5;
    if (node >= Nn) return;
    int lane = threadIdx.x & 31;
    int head = lane >> 3;

    float4 ad4 = *(const float4*)&g_ad[node * 4];
    float4 asl4 = *(const float4*)&g_as[node * 4];
    float adh[4] = {ad4.x, ad4.y, ad4.z, ad4.w};
    float ash[4] = {asl4.x, asl4.y, asl4.z, asl4.w};

    float m4[4];
#pragma unroll
    for (int hh = 0; hh < 4; hh++) m4[hh] = leaky(ash[hh] + adh[hh]);

    int beg = g_rowstart[node];
    int end = g_rowstart[node + 1];

    // pass 1: per-head max (lanes stride edges; unrolled for MLP)
#pragma unroll 4
    for (int j = beg + lane; j < end; j += 32) {
        int s = g_csrc[j];
        float4 a4 = *(const float4*)&g_as[s * 4];
        float av[4] = {a4.x, a4.y, a4.z, a4.w};
#pragma unroll
        for (int hh = 0; hh < 4; hh++) m4[hh] = fmaxf(m4[hh], leaky(av[hh] + adh[hh]));
    }
#pragma unroll
    for (int off = 16; off; off >>= 1) {
#pragma unroll
        for (int hh = 0; hh < 4; hh++)
            m4[hh] = fmaxf(m4[hh], __shfl_xor_sync(0xffffffffu, m4[hh], off));
    }

    float m = m4[head];
    float ad = adh[head];

    float p_self = __expf(leaky(ash[head] + ad) - m);
    float z = p_self;
    float4 hv = *(const float4*)&h[(size_t)node * HCC + lane * 4];
    float4 acc;
    acc.x = p_self * hv.x;
    acc.y = p_self * hv.y;
    acc.z = p_self * hv.z;
    acc.w = p_self * hv.w;

    // pass 2: gather + weighted sum, 4 edges per step for MLP≈8
    for (int j0 = beg; j0 < end; j0 += 32) {
        int myj = j0 + lane;
        int sj = (myj < end) ? g_csrc[myj] : 0;
        int cnt = min(32, end - j0);
        int t = 0;
        for (; t + 4 <= cnt; t += 4) {
            int s0 = __shfl_sync(0xffffffffu, sj, t);
            int s1 = __shfl_sync(0xffffffffu, sj, t + 1);
            int s2 = __shfl_sync(0xffffffffu, sj, t + 2);
            int s3 = __shfl_sync(0xffffffffu, sj, t + 3);
            float a0 = g_as[s0 * 4 + head];
            float a1 = g_as[s1 * 4 + head];
            float a2 = g_as[s2 * 4 + head];
            float a3 = g_as[s3 * 4 + head];
            float4 h0 = *(const float4*)&h[(size_t)s0 * HCC + lane * 4];
            float4 h1 = *(const float4*)&h[(size_t)s1 * HCC + lane * 4];
            float4 h2 = *(const float4*)&h[(size_t)s2 * HCC + lane * 4];
            float4 h3 = *(const float4*)&h[(size_t)s3 * HCC + lane * 4];
            float p0 = __expf(leaky(a0 + ad) - m);
            float p1 = __expf(leaky(a1 + ad) - m);
            float p2 = __expf(leaky(a2 + ad) - m);
            float p3 = __expf(leaky(a3 + ad) - m);
            z += (p0 + p1) + (p2 + p3);
            acc.x = fmaf(p0, h0.x, acc.x); acc.y = fmaf(p0, h0.y, acc.y);
            acc.z = fmaf(p0, h0.z, acc.z); acc.w = fmaf(p0, h0.w, acc.w);
            acc.x = fmaf(p1, h1.x, acc.x); acc.y = fmaf(p1, h1.y, acc.y);
            acc.z = fmaf(p1, h1.z, acc.z); acc.w = fmaf(p1, h1.w, acc.w);
            acc.x = fmaf(p2, h2.x, acc.x); acc.y = fmaf(p2, h2.y, acc.y);
            acc.z = fmaf(p2, h2.z, acc.z); acc.w = fmaf(p2, h2.w, acc.w);
            acc.x = fmaf(p3, h3.x, acc.x); acc.y = fmaf(p3, h3.y, acc.y);
            acc.z = fmaf(p3, h3.z, acc.z); acc.w = fmaf(p3, h3.w, acc.w);
        }
        for (; t < cnt; t++) {
            int s = __shfl_sync(0xffffffffu, sj, t);
            float a = g_as[s * 4 + head];
            float p = __expf(leaky(a + ad) - m);
            z += p;
            float4 h2 = *(const float4*)&h[(size_t)s * HCC + lane * 4];
            acc.x = fmaf(p, h2.x, acc.x);
            acc.y = fmaf(p, h2.y, acc.y);
            acc.z = fmaf(p, h2.z, acc.z);
            acc.w = fmaf(p, h2.w, acc.w);
        }
    }

    float inv = 1.f / z;
    float4 b4 = *(const float4*)&bias[lane * 4];
    float4 o;
    o.x = fmaxf(fmaf(acc.x, inv, b4.x), 0.f);
    o.y = fmaxf(fmaf(acc.y, inv, b4.y), 0.f);
    o.z = fmaxf(fmaf(acc.z, inv, b4.z), 0.f);
    o.w = fmaxf(fmaf(acc.w, inv, b4.w), 0.f);
    *(float4*)&out[(size_t)node * HCC + lane * 4] = o;
}

// ---------------- pooling ----------------
__global__ void k_cnt(const int* __restrict__ batch) {
    __shared__ int sc[NG];
    int t = threadIdx.x;
    if (t < NG) sc[t] = 0;
    __syncthreads();
    int i = blockIdx.x * SB + t;
    if (i < Nn) atomicAdd(&sc[batch[i]], 1);
    __syncthreads();
    if (t < NG && sc[t]) atomicAdd(&g_cnt[t], sc[t]);
}

__global__ void k_pool(const float* __restrict__ hf, const int* __restrict__ batch) {
    int t = threadIdx.x;
    int n0 = blockIdx.x * 64;
    if (n0 >= Nn) return;
    int n1 = min(n0 + 64, Nn);
    int cur = batch[n0];
    float acc = 0.f;
    for (int n = n0; n < n1; n++) {
        int bb = batch[n];
        if (bb != cur) {
            atomicAdd(&g_pool[cur * HCC + t], acc);
            acc = 0.f;
            cur = bb;
        }
        acc += hf[(size_t)n * HCC + t];
    }
    atomicAdd(&g_pool[cur * HCC + t], acc);
}

// ---------------- classifier ----------------
__global__ void k_classifier(const float* __restrict__ Wc1, const float* __restrict__ bc1,
                             const float* __restrict__ Wc2, const float* __restrict__ bc2,
                             float* __restrict__ out) {
    int g = blockIdx.x;
    int t = threadIdx.x;
    __shared__ float sg[HCC];
    __shared__ float sg1[CDIM];
    float inv = 1.f / (float)g_cnt[g];
    for (int c = t; c < HCC; c += 32) sg[c] = g_pool[g * HCC + c] * inv;
    __syncthreads();
    float a = bc1[t];
#pragma unroll 4
    for (int k = 0; k < HCC; k++) a = fmaf(sg[k], Wc1[k * CDIM + t], a);
    sg1[t] = a;
    __syncthreads();
    if (t < NCLS) {
        float b = bc2[t];
#pragma unroll
        for (int k = 0; k < CDIM; k++) b = fmaf(sg1[k], Wc2[k * NCLS + t], b);
        out[g * NCLS + t] = 1.f / (1.f + expf(-b));
    }
}

// ---------------- launch ----------------
extern "C" void kernel_launch(void* const* d_in, const int* in_sizes, int n_in,
                              void* d_out, int out_size) {
    const float* x    = (const float*)d_in[0];
    const int*   ei   = (const int*)d_in[1];
    const int*   batch= (const int*)d_in[2];
    const float* W1   = (const float*)d_in[3];
    const float* as1  = (const float*)d_in[4];
    const float* ad1  = (const float*)d_in[5];
    const float* b1   = (const float*)d_in[6];
    const float* W2   = (const float*)d_in[7];
    const float* as2  = (const float*)d_in[8];
    const float* ad2  = (const float*)d_in[9];
    const float* b2   = (const float*)d_in[10];
    const float* Wc1  = (const float*)d_in[11];
    const float* bc1  = (const float*)d_in[12];
    const float* Wc2  = (const float*)d_in[13];
    const float* bc2  = (const float*)d_in[14];
    float* out = (float*)d_out;

    int E = in_sizes[1] / 2;
    if (E > E_MAX) E = E_MAX;

    float *hP, *oP;
    cudaGetSymbolAddress((void**)&hP, g_h);
    cudaGetSymbolAddress((void**)&oP, g_o);

    int tpb = 256;
    int nodeWarpBlocks = (Nn * 32 + tpb - 1) / tpb;
    int mmaBlocks = (Nn + 127) / 128;
    int edge4Blocks = ((E + 3) / 4 + tpb - 1) / tpb;

    // GEMM-first ordering: layer-1 GEMM chain does not need the CSR, and this
    // places k_gemm_mma in the launch slot ncu has been profiling.
    k_splitB<F_IN><<<(F_IN * HCC + tpb - 1) / tpb, tpb>>>(W1);      // 1
    k_splitA<F_IN><<<(Nn * (F_IN / 2) + tpb - 1) / tpb, tpb>>>(x, Nn); // 2
    k_init<<<(Nn + tpb - 1) / tpb, tpb>>>();                        // 3
    k_gemm_mma<F_IN><<<mmaBlocks, 256>>>(hP, Nn);                   // 4
    k_alpha<<<nodeWarpBlocks, tpb>>>(hP, as1, ad1);                 // 5
    // CSR build
    k_deg<<<edge4Blocks, tpb>>>(ei, E);                             // 6
    k_scan1<<<NB, SB>>>();
    k_scan2<<<1, 128>>>();
    k_scan3<<<NB, SB>>>();
    k_scatter<<<edge4Blocks, tpb>>>(ei, E);

    // layer 1 aggregation
    k_aggregate<<<nodeWarpBlocks, tpb>>>(hP, b1, oP);

    // layer 2
    k_splitB<HCC><<<(HCC * HCC + tpb - 1) / tpb, tpb>>>(W2);
    k_splitA<HCC><<<(Nn * (HCC / 2) + tpb - 1) / tpb, tpb>>>(oP, Nn);
    k_gemm_mma<HCC><<<mmaBlocks, 256>>>(hP, Nn);
    k_alpha<<<nodeWarpBlocks, tpb>>>(hP, as2, ad2);
    k_aggregate<<<nodeWarpBlocks, tpb>>>(hP, b2, oP);

    // pooling + classifier
    k_cnt<<<NB, SB>>>(batch);
    k_pool<<<(Nn + 63) / 64, HCC>>>(oP, batch);
    k_classifier<<<NG, 32>>>(Wc1, bc1, Wc2, bc2, out);
}

// round 5
// speedup vs baseline: 1.4127x; 1.0047x over previous
#include <cuda_runtime.h>
#include <cuda_bf16.h>
#include <stdint.h>
#include <math.h>

#define Nn 50000
#define E_MAX 1600000
#define F_IN 256
#define HCC 128
#define NHEAD 4
#define CDIM 32
#define NG 64
#define NCLS 16
#define SB 512
#define NB ((Nn + SB - 1) / SB)   // 98

// ---------------- scratch (device globals; no allocation allowed) ----------
__device__ float g_h[(size_t)Nn * HCC];           // GEMM output fp32 (for alpha)
__device__ __nv_bfloat16 g_hb[(size_t)Nn * HCC];  // GEMM output bf16 (for gathers)
__device__ float g_o[(size_t)Nn * HCC];           // layer-2 aggregate out (pooling)
__device__ float g_as[Nn * NHEAD];
__device__ float g_ad[Nn * NHEAD];
__device__ int   g_deg[Nn];
__device__ int   g_rowstart[Nn + 1];
__device__ int   g_cur[Nn];
__device__ int   g_csrc[E_MAX];
__device__ int   g_bsum[NB];
__device__ int   g_boff[NB];
__device__ float g_pool[NG * HCC];
__device__ int   g_cnt[NG];
__device__ __nv_bfloat16 g_acat[(size_t)Nn * 2 * F_IN];   // GEMM A split [hi|lo]
__device__ __nv_bfloat16 g_bcat[HCC * 2 * F_IN];          // GEMM B split, transposed

// ---------------- cp.async helpers ----------------
__device__ __forceinline__ void cpa16(void* s, const void* g, int pred) {
    unsigned int sa = (unsigned int)__cvta_generic_to_shared(s);
    asm volatile(
        "{\n\t.reg .pred p;\n\t"
        "setp.ne.b32 p, %2, 0;\n\t"
        "@p cp.async.cg.shared.global [%0], [%1], 16;\n\t"
        "@!p cp.async.cg.shared.global [%0], [%1], 16, 0;\n\t}"
        :: "r"(sa), "l"(g), "r"(pred));
}
__device__ __forceinline__ void cpa16u(void* s, const void* g) {
    unsigned int sa = (unsigned int)__cvta_generic_to_shared(s);
    asm volatile("cp.async.cg.shared.global [%0], [%1], 16;" :: "r"(sa), "l"(g));
}

// ---------------- init ----------------
__global__ void k_init() {
    int i = blockIdx.x * blockDim.x + threadIdx.x;
    if (i < Nn) g_deg[i] = 0;
    if (i < NG * HCC) g_pool[i] = 0.f;
    if (i < NG) g_cnt[i] = 0;
}

// ---------------- CSR build ----------------
__global__ void k_deg(const int* __restrict__ ei, int E) {
    int e4 = (blockIdx.x * blockDim.x + threadIdx.x) * 4;
    if (e4 >= E) return;
    if (e4 + 3 < E && ((E & 3) == 0)) {
        int4 d = *(const int4*)&ei[E + e4];
        atomicAdd(&g_deg[d.x], 1);
        atomicAdd(&g_deg[d.y], 1);
        atomicAdd(&g_deg[d.z], 1);
        atomicAdd(&g_deg[d.w], 1);
    } else {
        for (int e = e4; e < min(e4 + 4, E); e++) atomicAdd(&g_deg[ei[E + e]], 1);
    }
}

__global__ void k_scan1() {
    __shared__ int s[SB];
    int t = threadIdx.x;
    int i = blockIdx.x * SB + t;
    s[t] = (i < Nn) ? g_deg[i] : 0;
    __syncthreads();
    for (int off = SB / 2; off; off >>= 1) {
        if (t < off) s[t] += s[t + off];
        __syncthreads();
    }
    if (t == 0) g_bsum[blockIdx.x] = s[0];
}

__global__ void k_scan2() {
    __shared__ int s[128];
    int t = threadIdx.x;
    int v = (t < NB) ? g_bsum[t] : 0;
    s[t] = v;
    __syncthreads();
    for (int off = 1; off < 128; off <<= 1) {
        int x = (t >= off) ? s[t - off] : 0;
        __syncthreads();
        s[t] += x;
        __syncthreads();
    }
    if (t < NB) g_boff[t] = s[t] - v;
    if (t == NB - 1) g_rowstart[Nn] = s[t];
}

__global__ void k_scan3() {
    __shared__ int s[SB];
    int t = threadIdx.x;
    int i = blockIdx.x * SB + t;
    int v = (i < Nn) ? g_deg[i] : 0;
    s[t] = v;
    __syncthreads();
    for (int off = 1; off < SB; off <<= 1) {
        int x = (t >= off) ? s[t - off] : 0;
        __syncthreads();
        s[t] += x;
        __syncthreads();
    }
    if (i < Nn) {
        int rs = g_boff[blockIdx.x] + s[t] - v;
        g_rowstart[i] = rs;
        g_cur[i] = rs;
    }
}

__global__ void k_scatter(const int* __restrict__ ei, int E) {
    int e4 = (blockIdx.x * blockDim.x + threadIdx.x) * 4;
    if (e4 >= E) return;
    if (e4 + 3 < E && ((E & 3) == 0)) {
        int4 s = *(const int4*)&ei[e4];
        int4 d = *(const int4*)&ei[E + e4];
        g_csrc[atomicAdd(&g_cur[d.x], 1)] = s.x;
        g_csrc[atomicAdd(&g_cur[d.y], 1)] = s.y;
        g_csrc[atomicAdd(&g_cur[d.z], 1)] = s.z;
        g_csrc[atomicAdd(&g_cur[d.w], 1)] = s.w;
    } else {
        for (int e = e4; e < min(e4 + 4, E); e++)
            g_csrc[atomicAdd(&g_cur[ei[E + e]], 1)] = ei[e];
    }
}

// ---------------- bf16x3 split staging ----------------
template <int K>
__global__ void k_splitA(const float* __restrict__ A, int M) {
    int idx = blockIdx.x * blockDim.x + threadIdx.x;
    if (idx >= M * (K / 2)) return;
    int r = idx / (K / 2);
    int c = (idx - r * (K / 2)) * 2;
    float2 v = *(const float2*)&A[(size_t)r * K + c];
    __nv_bfloat16 hx = __float2bfloat16(v.x);
    __nv_bfloat16 hy = __float2bfloat16(v.y);
    __nv_bfloat16 lx = __float2bfloat16(v.x - __bfloat162float(hx));
    __nv_bfloat16 ly = __float2bfloat16(v.y - __bfloat162float(hy));
    *(__nv_bfloat162*)&g_acat[(size_t)r * (2 * K) + c] = __nv_bfloat162(hx, hy);
    *(__nv_bfloat162*)&g_acat[(size_t)r * (2 * K) + K + c] = __nv_bfloat162(lx, ly);
}

template <int K>
__global__ void k_splitB(const float* __restrict__ B) {
    int idx = blockIdx.x * blockDim.x + threadIdx.x;
    if (idx >= K * HCC) return;
    int k = idx / HCC;
    int n = idx - k * HCC;
    float v = B[idx];
    __nv_bfloat16 h = __float2bfloat16(v);
    __nv_bfloat16 l = __float2bfloat16(v - __bfloat162float(h));
    g_bcat[(size_t)n * (2 * K) + k] = h;
    g_bcat[(size_t)n * (2 * K) + K + k] = l;
}

// ---------------- tensor-core GEMM (bf16x3, cp.async double-buffered) -------
// Writes fp32 C (for alpha) and bf16 copy Cb (for gathers).
#define SA 72
#define STAGE_ELEMS (128 * SA)
template <int K>
__global__ void k_gemm_mma(float* __restrict__ C, __nv_bfloat16* __restrict__ Cb, int M) {
    extern __shared__ __nv_bfloat16 sm[];
    __nv_bfloat16* As = sm;                       // 2 stages
    __nv_bfloat16* Bs = sm + 2 * STAGE_ELEMS;     // 2 stages
    const int tid = threadIdx.x;
    const int bm = blockIdx.x * 128;
    const int lane = tid & 31;
    const int warp = tid >> 5;
    const int wm = (warp & 3) * 32;
    const int wn = (warp >> 2) * 64;
    const int g = lane >> 2;
    const int t = lane & 3;
    const int A2K = 2 * K;
    const int NK = (3 * K) / 64;

    int crow[4], cq[4], cvalid[4];
    const __nv_bfloat16* asrcp[4];
#pragma unroll
    for (int i = 0; i < 4; i++) {
        int lin = tid + 256 * i;
        crow[i] = lin >> 3;
        cq[i] = lin & 7;
        cvalid[i] = (bm + crow[i] < M) ? 1 : 0;
        int r = cvalid[i] ? (bm + crow[i]) : 0;
        asrcp[i] = &g_acat[(size_t)r * A2K];
    }

    float acc[2][8][4];
#pragma unroll
    for (int mt = 0; mt < 2; mt++)
#pragma unroll
        for (int nt = 0; nt < 8; nt++)
#pragma unroll
            for (int r = 0; r < 4; r++) acc[mt][nt][r] = 0.f;

    auto issue = [&](int it, int st) {
        int kb = it * 64;
        int asrc = (kb < 2 * K) ? kb : kb - 2 * K;
        int bsrc = (kb < K) ? kb : kb - K;
        __nv_bfloat16* ab = As + st * STAGE_ELEMS;
        __nv_bfloat16* bb = Bs + st * STAGE_ELEMS;
#pragma unroll
        for (int i = 0; i < 4; i++)
            cpa16(&ab[crow[i] * SA + cq[i] * 8], asrcp[i] + asrc + cq[i] * 8, cvalid[i]);
#pragma unroll
        for (int i = 0; i < 4; i++)
            cpa16u(&bb[crow[i] * SA + cq[i] * 8],
                   &g_bcat[(size_t)crow[i] * A2K + bsrc + cq[i] * 8]);
        asm volatile("cp.async.commit_group;");
    };

    issue(0, 0);

    for (int it = 0; it < NK; it++) {
        if (it + 1 < NK) {
            issue(it + 1, (it + 1) & 1);
            asm volatile("cp.async.wait_group 1;");
        } else {
            asm volatile("cp.async.wait_group 0;");
        }
        __syncthreads();

        const __nv_bfloat16* ab = As + (it & 1) * STAGE_ELEMS;
        const __nv_bfloat16* bb = Bs + (it & 1) * STAGE_ELEMS;
#pragma unroll
        for (int s = 0; s < 4; s++) {
            int k0 = s * 16;
            unsigned a[2][4], b[8][2];
#pragma unroll
            for (int mt = 0; mt < 2; mt++) {
                int r0 = wm + mt * 16 + g;
                a[mt][0] = *(const unsigned*)&ab[r0 * SA + k0 + 2 * t];
                a[mt][1] = *(const unsigned*)&ab[(r0 + 8) * SA + k0 + 2 * t];
                a[mt][2] = *(const unsigned*)&ab[r0 * SA + k0 + 2 * t + 8];
                a[mt][3] = *(const unsigned*)&ab[(r0 + 8) * SA + k0 + 2 * t + 8];
            }
#pragma unroll
            for (int nt = 0; nt < 8; nt++) {
                int n0 = wn + nt * 8 + g;
                b[nt][0] = *(const unsigned*)&bb[n0 * SA + k0 + 2 * t];
                b[nt][1] = *(const unsigned*)&bb[n0 * SA + k0 + 2 * t + 8];
            }
#pragma unroll
            for (int mt = 0; mt < 2; mt++)
#pragma unroll
                for (int nt = 0; nt < 8; nt++) {
                    asm volatile(
                        "mma.sync.aligned.m16n8k16.row.col.f32.bf16.bf16.f32 "
                        "{%0,%1,%2,%3}, {%4,%5,%6,%7}, {%8,%9}, {%0,%1,%2,%3};"
                        : "+f"(acc[mt][nt][0]), "+f"(acc[mt][nt][1]),
                          "+f"(acc[mt][nt][2]), "+f"(acc[mt][nt][3])
                        : "r"(a[mt][0]), "r"(a[mt][1]), "r"(a[mt][2]), "r"(a[mt][3]),
                          "r"(b[nt][0]), "r"(b[nt][1]));
                }
        }
        __syncthreads();
    }

#pragma unroll
    for (int mt = 0; mt < 2; mt++) {
        int r0 = bm + wm + mt * 16 + g;
#pragma unroll
        for (int nt = 0; nt < 8; nt++) {
            int col = wn + nt * 8 + 2 * t;
            if (r0 < M) {
                *(float2*)&C[(size_t)r0 * HCC + col] =
                    make_float2(acc[mt][nt][0], acc[mt][nt][1]);
                *(__nv_bfloat162*)&Cb[(size_t)r0 * HCC + col] =
                    __nv_bfloat162(__float2bfloat16(acc[mt][nt][0]),
                                   __float2bfloat16(acc[mt][nt][1]));
            }
            if (r0 + 8 < M) {
                *(float2*)&C[(size_t)(r0 + 8) * HCC + col] =
                    make_float2(acc[mt][nt][2], acc[mt][nt][3]);
                *(__nv_bfloat162*)&Cb[(size_t)(r0 + 8) * HCC + col] =
                    __nv_bfloat162(__float2bfloat16(acc[mt][nt][2]),
                                   __float2bfloat16(acc[mt][nt][3]));
            }
        }
    }
}

// ---------------- per-node attention coefficients ----------------
__global__ void k_alpha(const float* __restrict__ h, const float* __restrict__ atts,
                        const float* __restrict__ attd) {
    int warp = (blockIdx.x * blockDim.x + threadIdx.x) >> 5;
    if (warp >= Nn) return;
    int lane = threadIdx.x & 31;
    float4 hv = *(const float4*)&h[(size_t)warp * HCC + lane * 4];
    float4 s4 = *(const float4*)&atts[lane * 4];
    float4 d4 = *(const float4*)&attd[lane * 4];
    float ps = hv.x * s4.x + hv.y * s4.y + hv.z * s4.z + hv.w * s4.w;
    float pd = hv.x * d4.x + hv.y * d4.y + hv.z * d4.z + hv.w * d4.w;
#pragma unroll
    for (int off = 4; off; off >>= 1) {
        ps += __shfl_down_sync(0xffffffffu, ps, off, 8);
        pd += __shfl_down_sync(0xffffffffu, pd, off, 8);
    }
    if ((lane & 7) == 0) {
        g_as[warp * 4 + (lane >> 3)] = ps;
        g_ad[warp * 4 + (lane >> 3)] = pd;
    }
}

__device__ __forceinline__ float leaky(float v) { return fmaxf(v, 0.2f * v); }

__device__ __forceinline__ void bf4_to_f(const __nv_bfloat16* p, float* f) {
    uint2 u = *(const uint2*)p;
    float2 a = __bfloat1622float2(*(const __nv_bfloat162*)&u.x);
    float2 b = __bfloat1622float2(*(const __nv_bfloat162*)&u.y);
    f[0] = a.x; f[1] = a.y; f[2] = b.x; f[3] = b.y;
}

// ---------------- pull-style GAT aggregation (bf16 gathers) ----------------
template <int SPLIT>
__global__ void k_aggregate(const __nv_bfloat16* __restrict__ hb,
                            const float* __restrict__ bias, float* __restrict__ out) {
    int node = (blockIdx.x * blockDim.x + threadIdx.x) >> 5;
    if (node >= Nn) return;
    int lane = threadIdx.x & 31;
    int head = lane >> 3;

    float4 ad4 = *(const float4*)&g_ad[node * 4];
    float4 asl4 = *(const float4*)&g_as[node * 4];
    float adh[4] = {ad4.x, ad4.y, ad4.z, ad4.w};
    float ash[4] = {asl4.x, asl4.y, asl4.z, asl4.w};

    float m4[4];
#pragma unroll
    for (int hh = 0; hh < 4; hh++) m4[hh] = leaky(ash[hh] + adh[hh]);

    int beg = g_rowstart[node];
    int end = g_rowstart[node + 1];

#pragma unroll 4
    for (int j = beg + lane; j < end; j += 32) {
        int s = g_csrc[j];
        float4 a4 = *(const float4*)&g_as[s * 4];
        float av[4] = {a4.x, a4.y, a4.z, a4.w};
#pragma unroll
        for (int hh = 0; hh < 4; hh++) m4[hh] = fmaxf(m4[hh], leaky(av[hh] + adh[hh]));
    }
#pragma unroll
    for (int off = 16; off; off >>= 1) {
#pragma unroll
        for (int hh = 0; hh < 4; hh++)
            m4[hh] = fmaxf(m4[hh], __shfl_xor_sync(0xffffffffu, m4[hh], off));
    }

    float m = m4[head];
    float ad = adh[head];

    float p_self = __expf(leaky(ash[head] + ad) - m);
    float z = p_self;
    float hv[4];
    bf4_to_f(&hb[(size_t)node * HCC + lane * 4], hv);
    float4 acc;
    acc.x = p_self * hv[0];
    acc.y = p_self * hv[1];
    acc.z = p_self * hv[2];
    acc.w = p_self * hv[3];

    for (int j0 = beg; j0 < end; j0 += 32) {
        int myj = j0 + lane;
        int sj = (myj < end) ? g_csrc[myj] : 0;
        int cnt = min(32, end - j0);
        int t = 0;
        for (; t + 4 <= cnt; t += 4) {
            int s0 = __shfl_sync(0xffffffffu, sj, t);
            int s1 = __shfl_sync(0xffffffffu, sj, t + 1);
            int s2 = __shfl_sync(0xffffffffu, sj, t + 2);
            int s3 = __shfl_sync(0xffffffffu, sj, t + 3);
            float a0 = g_as[s0 * 4 + head];
            float a1 = g_as[s1 * 4 + head];
            float a2 = g_as[s2 * 4 + head];
            float a3 = g_as[s3 * 4 + head];
            float h0[4], h1[4], h2[4], h3[4];
            bf4_to_f(&hb[(size_t)s0 * HCC + lane * 4], h0);
            bf4_to_f(&hb[(size_t)s1 * HCC + lane * 4], h1);
            bf4_to_f(&hb[(size_t)s2 * HCC + lane * 4], h2);
            bf4_to_f(&hb[(size_t)s3 * HCC + lane * 4], h3);
            float p0 = __expf(leaky(a0 + ad) - m);
            float p1 = __expf(leaky(a1 + ad) - m);
            float p2 = __expf(leaky(a2 + ad) - m);
            float p3 = __expf(leaky(a3 + ad) - m);
            z += (p0 + p1) + (p2 + p3);
            acc.x = fmaf(p0, h0[0], acc.x); acc.y = fmaf(p0, h0[1], acc.y);
            acc.z = fmaf(p0, h0[2], acc.z); acc.w = fmaf(p0, h0[3], acc.w);
            acc.x = fmaf(p1, h1[0], acc.x); acc.y = fmaf(p1, h1[1], acc.y);
            acc.z = fmaf(p1, h1[2], acc.z); acc.w = fmaf(p1, h1[3], acc.w);
            acc.x = fmaf(p2, h2[0], acc.x); acc.y = fmaf(p2, h2[1], acc.y);
            acc.z = fmaf(p2, h2[2], acc.z); acc.w = fmaf(p2, h2[3], acc.w);
            acc.x = fmaf(p3, h3[0], acc.x); acc.y = fmaf(p3, h3[1], acc.y);
            acc.z = fmaf(p3, h3[2], acc.z); acc.w = fmaf(p3, h3[3], acc.w);
        }
        for (; t < cnt; t++) {
            int s = __shfl_sync(0xffffffffu, sj, t);
            float a = g_as[s * 4 + head];
            float p = __expf(leaky(a + ad) - m);
            z += p;
            float h2[4];
            bf4_to_f(&hb[(size_t)s * HCC + lane * 4], h2);
            acc.x = fmaf(p, h2[0], acc.x);
            acc.y = fmaf(p, h2[1], acc.y);
            acc.z = fmaf(p, h2[2], acc.z);
            acc.w = fmaf(p, h2[3], acc.w);
        }
    }

    float inv = 1.f / z;
    float4 b4 = *(const float4*)&bias[lane * 4];
    float4 o;
    o.x = fmaxf(fmaf(acc.x, inv, b4.x), 0.f);
    o.y = fmaxf(fmaf(acc.y, inv, b4.y), 0.f);
    o.z = fmaxf(fmaf(acc.z, inv, b4.z), 0.f);
    o.w = fmaxf(fmaf(acc.w, inv, b4.w), 0.f);

    if (SPLIT) {
        __nv_bfloat16 hx = __float2bfloat16(o.x), hy = __float2bfloat16(o.y);
        __nv_bfloat16 hz = __float2bfloat16(o.z), hw = __float2bfloat16(o.w);
        __nv_bfloat16 lx = __float2bfloat16(o.x - __bfloat162float(hx));
        __nv_bfloat16 ly = __float2bfloat16(o.y - __bfloat162float(hy));
        __nv_bfloat16 lz = __float2bfloat16(o.z - __bfloat162float(hz));
        __nv_bfloat16 lw = __float2bfloat16(o.w - __bfloat162float(hw));
        size_t base = (size_t)node * 256 + lane * 4;
        *(__nv_bfloat162*)&g_acat[base] = __nv_bfloat162(hx, hy);
        *(__nv_bfloat162*)&g_acat[base + 2] = __nv_bfloat162(hz, hw);
        *(__nv_bfloat162*)&g_acat[base + 128] = __nv_bfloat162(lx, ly);
        *(__nv_bfloat162*)&g_acat[base + 130] = __nv_bfloat162(lz, lw);
    } else {
        *(float4*)&out[(size_t)node * HCC + lane * 4] = o;
    }
}

// ---------------- pooling ----------------
__global__ void k_cnt(const int* __restrict__ batch) {
    __shared__ int sc[NG];
    int t = threadIdx.x;
    if (t < NG) sc[t] = 0;
    __syncthreads();
    int i = blockIdx.x * SB + t;
    if (i < Nn) atomicAdd(&sc[batch[i]], 1);
    __syncthreads();
    if (t < NG && sc[t]) atomicAdd(&g_cnt[t], sc[t]);
}

__global__ void k_pool(const float* __restrict__ hf, const int* __restrict__ batch) {
    int t = threadIdx.x;
    int n0 = blockIdx.x * 64;
    if (n0 >= Nn) return;
    int n1 = min(n0 + 64, Nn);
    int cur = batch[n0];
    float acc = 0.f;
    for (int n = n0; n < n1; n++) {
        int bb = batch[n];
        if (bb != cur) {
            atomicAdd(&g_pool[cur * HCC + t], acc);
            acc = 0.f;
            cur = bb;
        }
        acc += hf[(size_t)n * HCC + t];
    }
    atomicAdd(&g_pool[cur * HCC + t], acc);
}

// ---------------- classifier ----------------
__global__ void k_classifier(const float* __restrict__ Wc1, const float* __restrict__ bc1,
                             const float* __restrict__ Wc2, const float* __restrict__ bc2,
                             float* __restrict__ out) {
    int g = blockIdx.x;
    int t = threadIdx.x;
    __shared__ float sg[HCC];
    __shared__ float sg1[CDIM];
    float inv = 1.f / (float)g_cnt[g];
    for (int c = t; c < HCC; c += 32) sg[c] = g_pool[g * HCC + c] * inv;
    __syncthreads();
    float a = bc1[t];
#pragma unroll 4
    for (int k = 0; k < HCC; k++) a = fmaf(sg[k], Wc1[k * CDIM + t], a);
    sg1[t] = a;
    __syncthreads();
    if (t < NCLS) {
        float b = bc2[t];
#pragma unroll
        for (int k = 0; k < CDIM; k++) b = fmaf(sg1[k], Wc2[k * NCLS + t], b);
        out[g * NCLS + t] = 1.f / (1.f + expf(-b));
    }
}

// ---------------- launch ----------------
extern "C" void kernel_launch(void* const* d_in, const int* in_sizes, int n_in,
                              void* d_out, int out_size) {
    const float* x    = (const float*)d_in[0];
    const int*   ei   = (const int*)d_in[1];
    const int*   batch= (const int*)d_in[2];
    const float* W1   = (const float*)d_in[3];
    const float* as1  = (const float*)d_in[4];
    const float* ad1  = (const float*)d_in[5];
    const float* b1   = (const float*)d_in[6];
    const float* W2   = (const float*)d_in[7];
    const float* as2  = (const float*)d_in[8];
    const float* ad2  = (const float*)d_in[9];
    const float* b2   = (const float*)d_in[10];
    const float* Wc1  = (const float*)d_in[11];
    const float* bc1  = (const float*)d_in[12];
    const float* Wc2  = (const float*)d_in[13];
    const float* bc2  = (const float*)d_in[14];
    float* out = (float*)d_out;

    int E = in_sizes[1] / 2;
    if (E > E_MAX) E = E_MAX;

    float *hP, *oP;
    __nv_bfloat16* hbP;
    cudaGetSymbolAddress((void**)&hP, g_h);
    cudaGetSymbolAddress((void**)&oP, g_o);
    cudaGetSymbolAddress((void**)&hbP, g_hb);

    const int smemBytes = 4 * STAGE_ELEMS * (int)sizeof(__nv_bfloat16);  // 73728
    static int attrDone = 0;
    if (!attrDone) {
        cudaFuncSetAttribute(k_gemm_mma<F_IN>, cudaFuncAttributeMaxDynamicSharedMemorySize, smemBytes);
        cudaFuncSetAttribute(k_gemm_mma<HCC>, cudaFuncAttributeMaxDynamicSharedMemorySize, smemBytes);
        attrDone = 1;
    }

    int tpb = 256;
    int nodeWarpBlocks = (Nn * 32 + tpb - 1) / tpb;
    int mmaBlocks = (Nn + 127) / 128;
    int edge4Blocks = ((E + 3) / 4 + tpb - 1) / tpb;

    k_splitB<F_IN><<<(F_IN * HCC + tpb - 1) / tpb, tpb>>>(W1);
    k_splitA<F_IN><<<(Nn * (F_IN / 2) + tpb - 1) / tpb, tpb>>>(x, Nn);
    k_init<<<(Nn + tpb - 1) / tpb, tpb>>>();
    k_gemm_mma<F_IN><<<mmaBlocks, 256, smemBytes>>>(hP, hbP, Nn);
    k_alpha<<<nodeWarpBlocks, tpb>>>(hP, as1, ad1);
    // CSR build
    k_deg<<<edge4Blocks, tpb>>>(ei, E);
    k_scan1<<<NB, SB>>>();
    k_scan2<<<1, 128>>>();
    k_scan3<<<NB, SB>>>();
    k_scatter<<<edge4Blocks, tpb>>>(ei, E);

    // layer 1 aggregation -> writes bf16 hi/lo split into g_acat
    k_aggregate<1><<<nodeWarpBlocks, tpb>>>(hbP, b1, oP);

    // layer 2
    k_splitB<HCC><<<(HCC * HCC + tpb - 1) / tpb, tpb>>>(W2);
    k_gemm_mma<HCC><<<mmaBlocks, 256, smemBytes>>>(hP, hbP, Nn);
    k_alpha<<<nodeWarpBlocks, tpb>>>(hP, as2, ad2);
    k_aggregate<0><<<nodeWarpBlocks, tpb>>>(hbP, b2, oP);

    // pooling + classifier
    k_cnt<<<NB, SB>>>(batch);
    k_pool<<<(Nn + 63) / 64, HCC>>>(oP, batch);
    k_classifier<<<NG, 32>>>(Wc1, bc1, Wc2, bc2, out);
}

// round 6
// speedup vs baseline: 1.5935x; 1.1280x over previous
#include <cuda_runtime.h>
#include <cuda_bf16.h>
#include <stdint.h>
#include <math.h>

#define Nn 50000
#define E_MAX 1600000
#define F_IN 256
#define HCC 128
#define NHEAD 4
#define CDIM 32
#define NG 64
#define NCLS 16
#define SB 512
#define NB ((Nn + SB - 1) / SB)   // 98

// ---------------- scratch (device globals; no allocation allowed) ----------
__device__ __nv_bfloat16 g_hb[(size_t)Nn * HCC];  // GEMM output bf16 (gathers)
__device__ float g_o[(size_t)Nn * HCC];           // layer-2 aggregate out
__device__ float g_as[Nn * NHEAD];
__device__ float g_ad[Nn * NHEAD];
__device__ int   g_deg[Nn];                        // zero at load; self-cleaning
__device__ int   g_rowstart[Nn + 1];
__device__ int   g_cur[Nn];
__device__ int   g_csrc[E_MAX];
__device__ int   g_bsum[NB];
__device__ float g_pool[NG * HCC];                 // zero at load; self-cleaning
__device__ int   g_cnt[NG];                        // zero at load; self-cleaning
__device__ __nv_bfloat16 g_acat[(size_t)Nn * 2 * F_IN];   // A split [hi|lo]
__device__ __nv_bfloat16 g_bcat[HCC * 2 * F_IN];          // W1 split, transposed
__device__ __nv_bfloat16 g_bcat2[HCC * 2 * HCC];          // W2 split, transposed

// ---------------- cp.async helpers ----------------
__device__ __forceinline__ void cpa16(void* s, const void* g, int pred) {
    unsigned int sa = (unsigned int)__cvta_generic_to_shared(s);
    asm volatile(
        "{\n\t.reg .pred p;\n\t"
        "setp.ne.b32 p, %2, 0;\n\t"
        "@p cp.async.cg.shared.global [%0], [%1], 16;\n\t"
        "@!p cp.async.cg.shared.global [%0], [%1], 16, 0;\n\t}"
        :: "r"(sa), "l"(g), "r"(pred));
}
__device__ __forceinline__ void cpa16u(void* s, const void* g) {
    unsigned int sa = (unsigned int)__cvta_generic_to_shared(s);
    asm volatile("cp.async.cg.shared.global [%0], [%1], 16;" :: "r"(sa), "l"(g));
}

// ---------------- CSR build ----------------
__global__ void k_deg(const int* __restrict__ ei, int E) {
    int e4 = (blockIdx.x * blockDim.x + threadIdx.x) * 4;
    if (e4 >= E) return;
    if (e4 + 3 < E && ((E & 3) == 0)) {
        int4 d = *(const int4*)&ei[E + e4];
        atomicAdd(&g_deg[d.x], 1);
        atomicAdd(&g_deg[d.y], 1);
        atomicAdd(&g_deg[d.z], 1);
        atomicAdd(&g_deg[d.w], 1);
    } else {
        for (int e = e4; e < min(e4 + 4, E); e++) atomicAdd(&g_deg[ei[E + e]], 1);
    }
}

// local exclusive scan per block; zeroes g_deg for next replay
__global__ void k_scanA() {
    __shared__ int s[SB];
    int t = threadIdx.x;
    int i = blockIdx.x * SB + t;
    int v = (i < Nn) ? g_deg[i] : 0;
    if (i < Nn) g_deg[i] = 0;
    s[t] = v;
    __syncthreads();
    for (int off = 1; off < SB; off <<= 1) {
        int x = (t >= off) ? s[t - off] : 0;
        __syncthreads();
        s[t] += x;
        __syncthreads();
    }
    if (i < Nn) g_rowstart[i] = s[t] - v;   // local exclusive
    if (t == SB - 1) g_bsum[blockIdx.x] = s[t];
}

// add block offsets (each block redundantly sums the 98 block sums)
__global__ void k_scanB() {
    __shared__ int sb[NB];
    __shared__ int soff;
    int t = threadIdx.x;
    int b = blockIdx.x;
    int i = b * SB + t;
    if (t < NB) sb[t] = g_bsum[t];
    __syncthreads();
    if (t == 0) {
        int o = 0;
        for (int j = 0; j < b; j++) o += sb[j];
        soff = o;
    }
    __syncthreads();
    int off = soff;
    if (i < Nn) {
        int rs = g_rowstart[i] + off;
        g_rowstart[i] = rs;
        g_cur[i] = rs;
    }
    if (b == NB - 1 && t == 0) g_rowstart[Nn] = off + sb[b];
}

__global__ void k_scatter(const int* __restrict__ ei, int E) {
    int e4 = (blockIdx.x * blockDim.x + threadIdx.x) * 4;
    if (e4 >= E) return;
    if (e4 + 3 < E && ((E & 3) == 0)) {
        int4 s = *(const int4*)&ei[e4];
        int4 d = *(const int4*)&ei[E + e4];
        g_csrc[atomicAdd(&g_cur[d.x], 1)] = s.x;
        g_csrc[atomicAdd(&g_cur[d.y], 1)] = s.y;
        g_csrc[atomicAdd(&g_cur[d.z], 1)] = s.z;
        g_csrc[atomicAdd(&g_cur[d.w], 1)] = s.w;
    } else {
        for (int e = e4; e < min(e4 + 4, E); e++)
            g_csrc[atomicAdd(&g_cur[ei[E + e]], 1)] = ei[e];
    }
}

// ---------------- fused split prep: x->g_acat, W1->g_bcat, W2->g_bcat2 -----
#define NA_PREP (Nn * (F_IN / 2))
__global__ void k_prep(const float* __restrict__ x, const float* __restrict__ W1,
                       const float* __restrict__ W2) {
    int idx = blockIdx.x * blockDim.x + threadIdx.x;
    if (idx < NA_PREP) {
        int r = idx / (F_IN / 2);
        int c = (idx - r * (F_IN / 2)) * 2;
        float2 v = *(const float2*)&x[(size_t)r * F_IN + c];
        __nv_bfloat16 hx = __float2bfloat16(v.x);
        __nv_bfloat16 hy = __float2bfloat16(v.y);
        __nv_bfloat16 lx = __float2bfloat16(v.x - __bfloat162float(hx));
        __nv_bfloat16 ly = __float2bfloat16(v.y - __bfloat162float(hy));
        *(__nv_bfloat162*)&g_acat[(size_t)r * (2 * F_IN) + c] = __nv_bfloat162(hx, hy);
        *(__nv_bfloat162*)&g_acat[(size_t)r * (2 * F_IN) + F_IN + c] = __nv_bfloat162(lx, ly);
    } else if (idx < NA_PREP + F_IN * HCC) {
        int j = idx - NA_PREP;
        int k = j / HCC;
        int n = j - k * HCC;
        float v = W1[j];
        __nv_bfloat16 h = __float2bfloat16(v);
        __nv_bfloat16 l = __float2bfloat16(v - __bfloat162float(h));
        g_bcat[(size_t)n * (2 * F_IN) + k] = h;
        g_bcat[(size_t)n * (2 * F_IN) + F_IN + k] = l;
    } else if (idx < NA_PREP + F_IN * HCC + HCC * HCC) {
        int j = idx - NA_PREP - F_IN * HCC;
        int k = j / HCC;
        int n = j - k * HCC;
        float v = W2[j];
        __nv_bfloat16 h = __float2bfloat16(v);
        __nv_bfloat16 l = __float2bfloat16(v - __bfloat162float(h));
        g_bcat2[(size_t)n * (2 * HCC) + k] = h;
        g_bcat2[(size_t)n * (2 * HCC) + HCC + k] = l;
    }
}

// ---------------- tensor-core GEMM (bf16x3) + fused alpha epilogue ---------
// Writes bf16 Cb only; computes g_as/g_ad (per-head attention dots) in epilogue.
#define SA 72
#define STAGE_ELEMS (128 * SA)
template <int K>
__global__ void k_gemm_mma(const __nv_bfloat16* __restrict__ Bmat,
                           __nv_bfloat16* __restrict__ Cb, int M,
                           const float* __restrict__ atts,
                           const float* __restrict__ attd) {
    extern __shared__ __nv_bfloat16 sm[];
    __nv_bfloat16* As = sm;
    __nv_bfloat16* Bs = sm + 2 * STAGE_ELEMS;
    const int tid = threadIdx.x;
    const int bm = blockIdx.x * 128;
    const int lane = tid & 31;
    const int warp = tid >> 5;
    const int wm = (warp & 3) * 32;
    const int wn = (warp >> 2) * 64;
    const int g = lane >> 2;
    const int t = lane & 3;
    const int A2K = 2 * K;
    const int NK = (3 * K) / 64;

    int crow[4], cq[4], cvalid[4];
    const __nv_bfloat16* asrcp[4];
#pragma unroll
    for (int i = 0; i < 4; i++) {
        int lin = tid + 256 * i;
        crow[i] = lin >> 3;
        cq[i] = lin & 7;
        cvalid[i] = (bm + crow[i] < M) ? 1 : 0;
        int r = cvalid[i] ? (bm + crow[i]) : 0;
        asrcp[i] = &g_acat[(size_t)r * A2K];
    }

    float acc[2][8][4];
#pragma unroll
    for (int mt = 0; mt < 2; mt++)
#pragma unroll
        for (int nt = 0; nt < 8; nt++)
#pragma unroll
            for (int r = 0; r < 4; r++) acc[mt][nt][r] = 0.f;

    auto issue = [&](int it, int st) {
        int kb = it * 64;
        int asrc = (kb < 2 * K) ? kb : kb - 2 * K;
        int bsrc = (kb < K) ? kb : kb - K;
        __nv_bfloat16* ab = As + st * STAGE_ELEMS;
        __nv_bfloat16* bb = Bs + st * STAGE_ELEMS;
#pragma unroll
        for (int i = 0; i < 4; i++)
            cpa16(&ab[crow[i] * SA + cq[i] * 8], asrcp[i] + asrc + cq[i] * 8, cvalid[i]);
#pragma unroll
        for (int i = 0; i < 4; i++)
            cpa16u(&bb[crow[i] * SA + cq[i] * 8],
                   &Bmat[(size_t)crow[i] * A2K + bsrc + cq[i] * 8]);
        asm volatile("cp.async.commit_group;");
    };

    issue(0, 0);

    for (int it = 0; it < NK; it++) {
        if (it + 1 < NK) {
            issue(it + 1, (it + 1) & 1);
            asm volatile("cp.async.wait_group 1;");
        } else {
            asm volatile("cp.async.wait_group 0;");
        }
        __syncthreads();

        const __nv_bfloat16* ab = As + (it & 1) * STAGE_ELEMS;
        const __nv_bfloat16* bb = Bs + (it & 1) * STAGE_ELEMS;
#pragma unroll
        for (int s = 0; s < 4; s++) {
            int k0 = s * 16;
            unsigned a[2][4], b[8][2];
#pragma unroll
            for (int mt = 0; mt < 2; mt++) {
                int r0 = wm + mt * 16 + g;
                a[mt][0] = *(const unsigned*)&ab[r0 * SA + k0 + 2 * t];
                a[mt][1] = *(const unsigned*)&ab[(r0 + 8) * SA + k0 + 2 * t];
                a[mt][2] = *(const unsigned*)&ab[r0 * SA + k0 + 2 * t + 8];
                a[mt][3] = *(const unsigned*)&ab[(r0 + 8) * SA + k0 + 2 * t + 8];
            }
#pragma unroll
            for (int nt = 0; nt < 8; nt++) {
                int n0 = wn + nt * 8 + g;
                b[nt][0] = *(const unsigned*)&bb[n0 * SA + k0 + 2 * t];
                b[nt][1] = *(const unsigned*)&bb[n0 * SA + k0 + 2 * t + 8];
            }
#pragma unroll
            for (int mt = 0; mt < 2; mt++)
#pragma unroll
                for (int nt = 0; nt < 8; nt++) {
                    asm volatile(
                        "mma.sync.aligned.m16n8k16.row.col.f32.bf16.bf16.f32 "
                        "{%0,%1,%2,%3}, {%4,%5,%6,%7}, {%8,%9}, {%0,%1,%2,%3};"
                        : "+f"(acc[mt][nt][0]), "+f"(acc[mt][nt][1]),
                          "+f"(acc[mt][nt][2]), "+f"(acc[mt][nt][3])
                        : "r"(a[mt][0]), "r"(a[mt][1]), "r"(a[mt][2]), "r"(a[mt][3]),
                          "r"(b[nt][0]), "r"(b[nt][1]));
                }
        }
        __syncthreads();
    }

    // ---- epilogue: write bf16 C + fused per-head alpha dots ----
    float* sAs = (float*)sm;          // 128 rows x 4 heads
    float* sAd = (float*)sm + 512;
    for (int i = tid; i < 1024; i += 256) ((float*)sm)[i] = 0.f;
    __syncthreads();

    const int hb0 = wn >> 5;
#pragma unroll
    for (int mt = 0; mt < 2; mt++) {
        int r0l = wm + mt * 16 + g;        // local row
        int row0 = bm + r0l;
        int row1 = row0 + 8;
        float s0[2] = {0.f, 0.f}, d0[2] = {0.f, 0.f};
        float s1[2] = {0.f, 0.f}, d1[2] = {0.f, 0.f};
#pragma unroll
        for (int nt = 0; nt < 8; nt++) {
            int c0 = wn + nt * 8 + 2 * t;
            int h = nt >> 2;
            float a0 = atts[c0], a1 = atts[c0 + 1];
            float b0 = attd[c0], b1 = attd[c0 + 1];
            s0[h] += acc[mt][nt][0] * a0 + acc[mt][nt][1] * a1;
            d0[h] += acc[mt][nt][0] * b0 + acc[mt][nt][1] * b1;
            s1[h] += acc[mt][nt][2] * a0 + acc[mt][nt][3] * a1;
            d1[h] += acc[mt][nt][2] * b0 + acc[mt][nt][3] * b1;
            if (row0 < M)
                *(__nv_bfloat162*)&Cb[(size_t)row0 * HCC + c0] =
                    __nv_bfloat162(__float2bfloat16(acc[mt][nt][0]),
                                   __float2bfloat16(acc[mt][nt][1]));
            if (row1 < M)
                *(__nv_bfloat162*)&Cb[(size_t)row1 * HCC + c0] =
                    __nv_bfloat162(__float2bfloat16(acc[mt][nt][2]),
                                   __float2bfloat16(acc[mt][nt][3]));
        }
#pragma unroll
        for (int h = 0; h < 2; h++) {
            atomicAdd(&sAs[r0l * 4 + hb0 + h], s0[h]);
            atomicAdd(&sAd[r0l * 4 + hb0 + h], d0[h]);
            atomicAdd(&sAs[(r0l + 8) * 4 + hb0 + h], s1[h]);
            atomicAdd(&sAd[(r0l + 8) * 4 + hb0 + h], d1[h]);
        }
    }
    __syncthreads();
    if (tid < 128 && bm + tid < M) {
        *(float4*)&g_as[(size_t)(bm + tid) * 4] = *(float4*)&sAs[tid * 4];
        *(float4*)&g_ad[(size_t)(bm + tid) * 4] = *(float4*)&sAd[tid * 4];
    }
}

__device__ __forceinline__ float leaky(float v) { return fmaxf(v, 0.2f * v); }

__device__ __forceinline__ void bf4_to_f(const __nv_bfloat16* p, float* f) {
    uint2 u = *(const uint2*)p;
    float2 a = __bfloat1622float2(*(const __nv_bfloat162*)&u.x);
    float2 b = __bfloat1622float2(*(const __nv_bfloat162*)&u.y);
    f[0] = a.x; f[1] = a.y; f[2] = b.x; f[3] = b.y;
}

// ---------------- pull-style GAT aggregation (bf16 gathers) ----------------
template <int SPLIT>
__global__ void k_aggregate(const __nv_bfloat16* __restrict__ hb,
                            const float* __restrict__ bias, float* __restrict__ out) {
    int node = (blockIdx.x * blockDim.x + threadIdx.x) >> 5;
    if (node >= Nn) return;
    int lane = threadIdx.x & 31;
    int head = lane >> 3;

    float4 ad4 = *(const float4*)&g_ad[node * 4];
    float4 asl4 = *(const float4*)&g_as[node * 4];
    float adh[4] = {ad4.x, ad4.y, ad4.z, ad4.w};
    float ash[4] = {asl4.x, asl4.y, asl4.z, asl4.w};

    float m4[4];
#pragma unroll
    for (int hh = 0; hh < 4; hh++) m4[hh] = leaky(ash[hh] + adh[hh]);

    int beg = g_rowstart[node];
    int end = g_rowstart[node + 1];

#pragma unroll 4
    for (int j = beg + lane; j < end; j += 32) {
        int s = g_csrc[j];
        float4 a4 = *(const float4*)&g_as[s * 4];
        float av[4] = {a4.x, a4.y, a4.z, a4.w};
#pragma unroll
        for (int hh = 0; hh < 4; hh++) m4[hh] = fmaxf(m4[hh], leaky(av[hh] + adh[hh]));
    }
#pragma unroll
    for (int off = 16; off; off >>= 1) {
#pragma unroll
        for (int hh = 0; hh < 4; hh++)
            m4[hh] = fmaxf(m4[hh], __shfl_xor_sync(0xffffffffu, m4[hh], off));
    }

    float m = m4[head];
    float ad = adh[head];

    float p_self = __expf(leaky(ash[head] + ad) - m);
    float z = p_self;
    float hv[4];
    bf4_to_f(&hb[(size_t)node * HCC + lane * 4], hv);
    float4 acc;
    acc.x = p_self * hv[0];
    acc.y = p_self * hv[1];
    acc.z = p_self * hv[2];
    acc.w = p_self * hv[3];

    for (int j0 = beg; j0 < end; j0 += 32) {
        int myj = j0 + lane;
        int sj = (myj < end) ? g_csrc[myj] : 0;
        int cnt = min(32, end - j0);
        int t = 0;
        for (; t + 4 <= cnt; t += 4) {
            int s0 = __shfl_sync(0xffffffffu, sj, t);
            int s1 = __shfl_sync(0xffffffffu, sj, t + 1);
            int s2 = __shfl_sync(0xffffffffu, sj, t + 2);
            int s3 = __shfl_sync(0xffffffffu, sj, t + 3);
            float a0 = g_as[s0 * 4 + head];
            float a1 = g_as[s1 * 4 + head];
            float a2 = g_as[s2 * 4 + head];
            float a3 = g_as[s3 * 4 + head];
            float h0[4], h1[4], h2[4], h3[4];
            bf4_to_f(&hb[(size_t)s0 * HCC + lane * 4], h0);
            bf4_to_f(&hb[(size_t)s1 * HCC + lane * 4], h1);
            bf4_to_f(&hb[(size_t)s2 * HCC + lane * 4], h2);
            bf4_to_f(&hb[(size_t)s3 * HCC + lane * 4], h3);
            float p0 = __expf(leaky(a0 + ad) - m);
            float p1 = __expf(leaky(a1 + ad) - m);
            float p2 = __expf(leaky(a2 + ad) - m);
            float p3 = __expf(leaky(a3 + ad) - m);
            z += (p0 + p1) + (p2 + p3);
            acc.x = fmaf(p0, h0[0], acc.x); acc.y = fmaf(p0, h0[1], acc.y);
            acc.z = fmaf(p0, h0[2], acc.z); acc.w = fmaf(p0, h0[3], acc.w);
            acc.x = fmaf(p1, h1[0], acc.x); acc.y = fmaf(p1, h1[1], acc.y);
            acc.z = fmaf(p1, h1[2], acc.z); acc.w = fmaf(p1, h1[3], acc.w);
            acc.x = fmaf(p2, h2[0], acc.x); acc.y = fmaf(p2, h2[1], acc.y);
            acc.z = fmaf(p2, h2[2], acc.z); acc.w = fmaf(p2, h2[3], acc.w);
            acc.x = fmaf(p3, h3[0], acc.x); acc.y = fmaf(p3, h3[1], acc.y);
            acc.z = fmaf(p3, h3[2], acc.z); acc.w = fmaf(p3, h3[3], acc.w);
        }
        for (; t < cnt; t++) {
            int s = __shfl_sync(0xffffffffu, sj, t);
            float a = g_as[s * 4 + head];
            float p = __expf(leaky(a + ad) - m);
            z += p;
            float h2[4];
            bf4_to_f(&hb[(size_t)s * HCC + lane * 4], h2);
            acc.x = fmaf(p, h2[0], acc.x);
            acc.y = fmaf(p, h2[1], acc.y);
            acc.z = fmaf(p, h2[2], acc.z);
            acc.w = fmaf(p, h2[3], acc.w);
        }
    }

    float inv = 1.f / z;
    float4 b4 = *(const float4*)&bias[lane * 4];
    float4 o;
    o.x = fmaxf(fmaf(acc.x, inv, b4.x), 0.f);
    o.y = fmaxf(fmaf(acc.y, inv, b4.y), 0.f);
    o.z = fmaxf(fmaf(acc.z, inv, b4.z), 0.f);
    o.w = fmaxf(fmaf(acc.w, inv, b4.w), 0.f);

    if (SPLIT) {
        __nv_bfloat16 hx = __float2bfloat16(o.x), hy = __float2bfloat16(o.y);
        __nv_bfloat16 hz = __float2bfloat16(o.z), hw = __float2bfloat16(o.w);
        __nv_bfloat16 lx = __float2bfloat16(o.x - __bfloat162float(hx));
        __nv_bfloat16 ly = __float2bfloat16(o.y - __bfloat162float(hy));
        __nv_bfloat16 lz = __float2bfloat16(o.z - __bfloat162float(hz));
        __nv_bfloat16 lw = __float2bfloat16(o.w - __bfloat162float(hw));
        size_t base = (size_t)node * 256 + lane * 4;
        *(__nv_bfloat162*)&g_acat[base] = __nv_bfloat162(hx, hy);
        *(__nv_bfloat162*)&g_acat[base + 2] = __nv_bfloat162(hz, hw);
        *(__nv_bfloat162*)&g_acat[base + 128] = __nv_bfloat162(lx, ly);
        *(__nv_bfloat162*)&g_acat[base + 130] = __nv_bfloat162(lz, lw);
    } else {
        *(float4*)&out[(size_t)node * HCC + lane * 4] = o;
    }
}

// ---------------- pooling (count fused) ----------------
__global__ void k_pool(const float* __restrict__ hf, const int* __restrict__ batch) {
    __shared__ int sc[NG];
    int t = threadIdx.x;
    int n0 = blockIdx.x * 64;
    if (n0 >= Nn) return;
    int n1 = min(n0 + 64, Nn);
    if (t < NG) sc[t] = 0;
    __syncthreads();
    if (t < 64 && n0 + t < n1) atomicAdd(&sc[batch[n0 + t]], 1);
    __syncthreads();
    if (t < NG && sc[t]) atomicAdd(&g_cnt[t], sc[t]);

    int cur = batch[n0];
    float acc = 0.f;
    for (int n = n0; n < n1; n++) {
        int bb = batch[n];
        if (bb != cur) {
            atomicAdd(&g_pool[cur * HCC + t], acc);
            acc = 0.f;
            cur = bb;
        }
        acc += hf[(size_t)n * HCC + t];
    }
    atomicAdd(&g_pool[cur * HCC + t], acc);
}

// ---------------- classifier (self-cleans g_pool/g_cnt) ----------------
__global__ void k_classifier(const float* __restrict__ Wc1, const float* __restrict__ bc1,
                             const float* __restrict__ Wc2, const float* __restrict__ bc2,
                             float* __restrict__ out) {
    int g = blockIdx.x;
    int t = threadIdx.x;
    __shared__ float sg[HCC];
    __shared__ float sg1[CDIM];
    float inv = 1.f / (float)g_cnt[g];
    for (int c = t; c < HCC; c += 32) sg[c] = g_pool[g * HCC + c] * inv;
    __syncthreads();
    // self-clean for next replay
    for (int c = t; c < HCC; c += 32) g_pool[g * HCC + c] = 0.f;
    if (t == 0) g_cnt[g] = 0;
    float a = bc1[t];
#pragma unroll 4
    for (int k = 0; k < HCC; k++) a = fmaf(sg[k], Wc1[k * CDIM + t], a);
    sg1[t] = a;
    __syncthreads();
    if (t < NCLS) {
        float b = bc2[t];
#pragma unroll
        for (int k = 0; k < CDIM; k++) b = fmaf(sg1[k], Wc2[k * NCLS + t], b);
        out[g * NCLS + t] = 1.f / (1.f + expf(-b));
    }
}

// ---------------- launch ----------------
extern "C" void kernel_launch(void* const* d_in, const int* in_sizes, int n_in,
                              void* d_out, int out_size) {
    const float* x    = (const float*)d_in[0];
    const int*   ei   = (const int*)d_in[1];
    const int*   batch= (const int*)d_in[2];
    const float* as1  = (const float*)d_in[4];
    const float* ad1  = (const float*)d_in[5];
    const float* b1   = (const float*)d_in[6];
    const float* as2  = (const float*)d_in[8];
    const float* ad2  = (const float*)d_in[9];
    const float* b2   = (const float*)d_in[10];
    const float* Wc1  = (const float*)d_in[11];
    const float* bc1  = (const float*)d_in[12];
    const float* Wc2  = (const float*)d_in[13];
    const float* bc2  = (const float*)d_in[14];
    const float* W1   = (const float*)d_in[3];
    const float* W2   = (const float*)d_in[7];
    float* out = (float*)d_out;

    int E = in_sizes[1] / 2;
    if (E > E_MAX) E = E_MAX;

    float* oP;
    __nv_bfloat16 *hbP, *bc1P, *bc2P;
    cudaGetSymbolAddress((void**)&oP, g_o);
    cudaGetSymbolAddress((void**)&hbP, g_hb);
    cudaGetSymbolAddress((void**)&bc1P, g_bcat);
    cudaGetSymbolAddress((void**)&bc2P, g_bcat2);

    const int smemBytes = 4 * STAGE_ELEMS * (int)sizeof(__nv_bfloat16);  // 73728

    static cudaStream_t s2 = 0;
    static cudaEvent_t evF = 0, evJ = 0;
    static int inited = 0;
    if (!inited) {
        cudaFuncSetAttribute(k_gemm_mma<F_IN>, cudaFuncAttributeMaxDynamicSharedMemorySize, smemBytes);
        cudaFuncSetAttribute(k_gemm_mma<HCC>, cudaFuncAttributeMaxDynamicSharedMemorySize, smemBytes);
        cudaStreamCreateWithFlags(&s2, cudaStreamNonBlocking);
        cudaEventCreateWithFlags(&evF, cudaEventDisableTiming);
        cudaEventCreateWithFlags(&evJ, cudaEventDisableTiming);
        inited = 1;
    }

    int tpb = 256;
    int nodeWarpBlocks = (Nn * 32 + tpb - 1) / tpb;
    int mmaBlocks = (Nn + 127) / 128;
    int edge4Blocks = ((E + 3) / 4 + tpb - 1) / tpb;
    int prepBlocks = (NA_PREP + F_IN * HCC + HCC * HCC + tpb - 1) / tpb;

    // fork: CSR build on s2 concurrent with prep+GEMM1 on main stream
    cudaEventRecord(evF, 0);
    cudaStreamWaitEvent(s2, evF, 0);
    k_deg<<<edge4Blocks, tpb, 0, s2>>>(ei, E);
    k_scanA<<<NB, SB, 0, s2>>>();
    k_scanB<<<NB, SB, 0, s2>>>();
    k_scatter<<<edge4Blocks, tpb, 0, s2>>>(ei, E);
    cudaEventRecord(evJ, s2);

    // main stream: prep + layer-1 GEMM (alpha fused)
    k_prep<<<prepBlocks, tpb>>>(x, W1, W2);
    k_gemm_mma<F_IN><<<mmaBlocks, 256, smemBytes>>>(bc1P, hbP, Nn, as1, ad1);

    // join
    cudaStreamWaitEvent(0, evJ, 0);

    // layer-1 aggregate (writes bf16 hi/lo split into g_acat)
    k_aggregate<1><<<nodeWarpBlocks, tpb>>>(hbP, b1, oP);

    // layer 2
    k_gemm_mma<HCC><<<mmaBlocks, 256, smemBytes>>>(bc2P, hbP, Nn, as2, ad2);
    k_aggregate<0><<<nodeWarpBlocks, tpb>>>(hbP, b2, oP);

    // pooling + classifier
    k_pool<<<(Nn + 63) / 64, HCC>>>(oP, batch);
    k_classifier<<<NG, 32>>>(Wc1, bc1, Wc2, bc2, out);
}

// round 7
// speedup vs baseline: 1.6228x; 1.0184x over previous
#include <cuda_runtime.h>
#include <cuda_bf16.h>
#include <stdint.h>
#include <math.h>

#define Nn 50000
#define E_MAX 1600000
#define F_IN 256
#define HCC 128
#define NHEAD 4
#define CDIM 32
#define NG 64
#define NCLS 16
#define SB 512
#define NB ((Nn + SB - 1) / SB)   // 98

// ---------------- scratch (device globals; no allocation allowed) ----------
__device__ __nv_bfloat16 g_hb[(size_t)Nn * HCC];  // GEMM output bf16 (gathers)
__device__ float g_o[(size_t)Nn * HCC];           // layer-2 aggregate out
__device__ float g_as[Nn * NHEAD];
__device__ float g_ad[Nn * NHEAD];
__device__ int   g_deg[Nn];                        // zero at load; self-cleaning
__device__ int   g_rowstart[Nn + 1];
__device__ int   g_cur[Nn];
__device__ int   g_csrc[E_MAX];
__device__ int   g_bsum[NB];
__device__ float g_pool[NG * HCC];                 // zero at load; self-cleaning
__device__ int   g_cnt[NG];                        // zero at load; self-cleaning
__device__ __nv_bfloat16 g_acat[(size_t)Nn * 2 * F_IN];   // A split [hi|lo]
__device__ __nv_bfloat16 g_bcat[HCC * 2 * F_IN];          // W1 split, transposed
__device__ __nv_bfloat16 g_bcat2[HCC * 2 * HCC];          // W2 split, transposed

// ---------------- cp.async helpers ----------------
__device__ __forceinline__ void cpa16(void* s, const void* g, int pred) {
    unsigned int sa = (unsigned int)__cvta_generic_to_shared(s);
    asm volatile(
        "{\n\t.reg .pred p;\n\t"
        "setp.ne.b32 p, %2, 0;\n\t"
        "@p cp.async.cg.shared.global [%0], [%1], 16;\n\t"
        "@!p cp.async.cg.shared.global [%0], [%1], 16, 0;\n\t}"
        :: "r"(sa), "l"(g), "r"(pred));
}
__device__ __forceinline__ void cpa16u(void* s, const void* g) {
    unsigned int sa = (unsigned int)__cvta_generic_to_shared(s);
    asm volatile("cp.async.cg.shared.global [%0], [%1], 16;" :: "r"(sa), "l"(g));
}

// ---------------- CSR build ----------------
__global__ void k_deg(const int* __restrict__ ei, int E) {
    int e4 = (blockIdx.x * blockDim.x + threadIdx.x) * 4;
    if (e4 >= E) return;
    if (e4 + 3 < E && ((E & 3) == 0)) {
        int4 d = *(const int4*)&ei[E + e4];
        atomicAdd(&g_deg[d.x], 1);
        atomicAdd(&g_deg[d.y], 1);
        atomicAdd(&g_deg[d.z], 1);
        atomicAdd(&g_deg[d.w], 1);
    } else {
        for (int e = e4; e < min(e4 + 4, E); e++) atomicAdd(&g_deg[ei[E + e]], 1);
    }
}

// local exclusive scan per block; zeroes g_deg for next replay
__global__ void k_scanA() {
    __shared__ int s[SB];
    int t = threadIdx.x;
    int i = blockIdx.x * SB + t;
    int v = (i < Nn) ? g_deg[i] : 0;
    if (i < Nn) g_deg[i] = 0;
    s[t] = v;
    __syncthreads();
    for (int off = 1; off < SB; off <<= 1) {
        int x = (t >= off) ? s[t - off] : 0;
        __syncthreads();
        s[t] += x;
        __syncthreads();
    }
    if (i < Nn) g_rowstart[i] = s[t] - v;   // local exclusive
    if (t == SB - 1) g_bsum[blockIdx.x] = s[t];
}

// add block offsets (each block redundantly sums the 98 block sums)
__global__ void k_scanB() {
    __shared__ int sb[NB];
    __shared__ int soff;
    int t = threadIdx.x;
    int b = blockIdx.x;
    int i = b * SB + t;
    if (t < NB) sb[t] = g_bsum[t];
    __syncthreads();
    if (t == 0) {
        int o = 0;
        for (int j = 0; j < b; j++) o += sb[j];
        soff = o;
    }
    __syncthreads();
    int off = soff;
    if (i < Nn) {
        int rs = g_rowstart[i] + off;
        g_rowstart[i] = rs;
        g_cur[i] = rs;
    }
    if (b == NB - 1 && t == 0) g_rowstart[Nn] = off + sb[b];
}

__global__ void k_scatter(const int* __restrict__ ei, int E) {
    int e4 = (blockIdx.x * blockDim.x + threadIdx.x) * 4;
    if (e4 >= E) return;
    if (e4 + 3 < E && ((E & 3) == 0)) {
        int4 s = *(const int4*)&ei[e4];
        int4 d = *(const int4*)&ei[E + e4];
        g_csrc[atomicAdd(&g_cur[d.x], 1)] = s.x;
        g_csrc[atomicAdd(&g_cur[d.y], 1)] = s.y;
        g_csrc[atomicAdd(&g_cur[d.z], 1)] = s.z;
        g_csrc[atomicAdd(&g_cur[d.w], 1)] = s.w;
    } else {
        for (int e = e4; e < min(e4 + 4, E); e++)
            g_csrc[atomicAdd(&g_cur[ei[E + e]], 1)] = ei[e];
    }
}

// ---------------- fused split prep: x->g_acat, W1->g_bcat, W2->g_bcat2 -----
#define NA_PREP (Nn * (F_IN / 2))
__global__ void k_prep(const float* __restrict__ x, const float* __restrict__ W1,
                       const float* __restrict__ W2) {
    int idx = blockIdx.x * blockDim.x + threadIdx.x;
    if (idx < NA_PREP) {
        int r = idx / (F_IN / 2);
        int c = (idx - r * (F_IN / 2)) * 2;
        float2 v = *(const float2*)&x[(size_t)r * F_IN + c];
        __nv_bfloat16 hx = __float2bfloat16(v.x);
        __nv_bfloat16 hy = __float2bfloat16(v.y);
        __nv_bfloat16 lx = __float2bfloat16(v.x - __bfloat162float(hx));
        __nv_bfloat16 ly = __float2bfloat16(v.y - __bfloat162float(hy));
        *(__nv_bfloat162*)&g_acat[(size_t)r * (2 * F_IN) + c] = __nv_bfloat162(hx, hy);
        *(__nv_bfloat162*)&g_acat[(size_t)r * (2 * F_IN) + F_IN + c] = __nv_bfloat162(lx, ly);
    } else if (idx < NA_PREP + F_IN * HCC) {
        int j = idx - NA_PREP;
        int k = j / HCC;
        int n = j - k * HCC;
        float v = W1[j];
        __nv_bfloat16 h = __float2bfloat16(v);
        __nv_bfloat16 l = __float2bfloat16(v - __bfloat162float(h));
        g_bcat[(size_t)n * (2 * F_IN) + k] = h;
        g_bcat[(size_t)n * (2 * F_IN) + F_IN + k] = l;
    } else if (idx < NA_PREP + F_IN * HCC + HCC * HCC) {
        int j = idx - NA_PREP - F_IN * HCC;
        int k = j / HCC;
        int n = j - k * HCC;
        float v = W2[j];
        __nv_bfloat16 h = __float2bfloat16(v);
        __nv_bfloat16 l = __float2bfloat16(v - __bfloat162float(h));
        g_bcat2[(size_t)n * (2 * HCC) + k] = h;
        g_bcat2[(size_t)n * (2 * HCC) + HCC + k] = l;
    }
}

// ---------------- tensor-core GEMM (bf16x3) + fused alpha epilogue ---------
#define SA 72
#define STAGE_ELEMS (128 * SA)
template <int K>
__global__ void k_gemm_mma(const __nv_bfloat16* __restrict__ Bmat,
                           __nv_bfloat16* __restrict__ Cb, int M,
                           const float* __restrict__ atts,
                           const float* __restrict__ attd) {
    extern __shared__ __nv_bfloat16 sm[];
    __nv_bfloat16* As = sm;
    __nv_bfloat16* Bs = sm + 2 * STAGE_ELEMS;
    const int tid = threadIdx.x;
    const int bm = blockIdx.x * 128;
    const int lane = tid & 31;
    const int warp = tid >> 5;
    const int wm = (warp & 3) * 32;
    const int wn = (warp >> 2) * 64;
    const int g = lane >> 2;
    const int t = lane & 3;
    const int A2K = 2 * K;
    const int NK = (3 * K) / 64;

    int crow[4], cq[4], cvalid[4];
    const __nv_bfloat16* asrcp[4];
#pragma unroll
    for (int i = 0; i < 4; i++) {
        int lin = tid + 256 * i;
        crow[i] = lin >> 3;
        cq[i] = lin & 7;
        cvalid[i] = (bm + crow[i] < M) ? 1 : 0;
        int r = cvalid[i] ? (bm + crow[i]) : 0;
        asrcp[i] = &g_acat[(size_t)r * A2K];
    }

    float acc[2][8][4];
#pragma unroll
    for (int mt = 0; mt < 2; mt++)
#pragma unroll
        for (int nt = 0; nt < 8; nt++)
#pragma unroll
            for (int r = 0; r < 4; r++) acc[mt][nt][r] = 0.f;

    auto issue = [&](int it, int st) {
        int kb = it * 64;
        int asrc = (kb < 2 * K) ? kb : kb - 2 * K;
        int bsrc = (kb < K) ? kb : kb - K;
        __nv_bfloat16* ab = As + st * STAGE_ELEMS;
        __nv_bfloat16* bb = Bs + st * STAGE_ELEMS;
#pragma unroll
        for (int i = 0; i < 4; i++)
            cpa16(&ab[crow[i] * SA + cq[i] * 8], asrcp[i] + asrc + cq[i] * 8, cvalid[i]);
#pragma unroll
        for (int i = 0; i < 4; i++)
            cpa16u(&bb[crow[i] * SA + cq[i] * 8],
                   &Bmat[(size_t)crow[i] * A2K + bsrc + cq[i] * 8]);
        asm volatile("cp.async.commit_group;");
    };

    issue(0, 0);

    for (int it = 0; it < NK; it++) {
        if (it + 1 < NK) {
            issue(it + 1, (it + 1) & 1);
            asm volatile("cp.async.wait_group 1;");
        } else {
            asm volatile("cp.async.wait_group 0;");
        }
        __syncthreads();

        const __nv_bfloat16* ab = As + (it & 1) * STAGE_ELEMS;
        const __nv_bfloat16* bb = Bs + (it & 1) * STAGE_ELEMS;
#pragma unroll
        for (int s = 0; s < 4; s++) {
            int k0 = s * 16;
            unsigned a[2][4], b[8][2];
#pragma unroll
            for (int mt = 0; mt < 2; mt++) {
                int r0 = wm + mt * 16 + g;
                a[mt][0] = *(const unsigned*)&ab[r0 * SA + k0 + 2 * t];
                a[mt][1] = *(const unsigned*)&ab[(r0 + 8) * SA + k0 + 2 * t];
                a[mt][2] = *(const unsigned*)&ab[r0 * SA + k0 + 2 * t + 8];
                a[mt][3] = *(const unsigned*)&ab[(r0 + 8) * SA + k0 + 2 * t + 8];
            }
#pragma unroll
            for (int nt = 0; nt < 8; nt++) {
                int n0 = wn + nt * 8 + g;
                b[nt][0] = *(const unsigned*)&bb[n0 * SA + k0 + 2 * t];
                b[nt][1] = *(const unsigned*)&bb[n0 * SA + k0 + 2 * t + 8];
            }
#pragma unroll
            for (int mt = 0; mt < 2; mt++)
#pragma unroll
                for (int nt = 0; nt < 8; nt++) {
                    asm volatile(
                        "mma.sync.aligned.m16n8k16.row.col.f32.bf16.bf16.f32 "
                        "{%0,%1,%2,%3}, {%4,%5,%6,%7}, {%8,%9}, {%0,%1,%2,%3};"
                        : "+f"(acc[mt][nt][0]), "+f"(acc[mt][nt][1]),
                          "+f"(acc[mt][nt][2]), "+f"(acc[mt][nt][3])
                        : "r"(a[mt][0]), "r"(a[mt][1]), "r"(a[mt][2]), "r"(a[mt][3]),
                          "r"(b[nt][0]), "r"(b[nt][1]));
                }
        }
        __syncthreads();
    }

    // ---- epilogue: write bf16 C + fused per-head alpha dots ----
    float* sAs = (float*)sm;          // 128 rows x 4 heads
    float* sAd = (float*)sm + 512;
    for (int i = tid; i < 1024; i += 256) ((float*)sm)[i] = 0.f;
    __syncthreads();

    const int hb0 = wn >> 5;
#pragma unroll
    for (int mt = 0; mt < 2; mt++) {
        int r0l = wm + mt * 16 + g;
        int row0 = bm + r0l;
        int row1 = row0 + 8;
        float s0[2] = {0.f, 0.f}, d0[2] = {0.f, 0.f};
        float s1[2] = {0.f, 0.f}, d1[2] = {0.f, 0.f};
#pragma unroll
        for (int nt = 0; nt < 8; nt++) {
            int c0 = wn + nt * 8 + 2 * t;
            int h = nt >> 2;
            float a0 = atts[c0], a1 = atts[c0 + 1];
            float b0 = attd[c0], b1 = attd[c0 + 1];
            s0[h] += acc[mt][nt][0] * a0 + acc[mt][nt][1] * a1;
            d0[h] += acc[mt][nt][0] * b0 + acc[mt][nt][1] * b1;
            s1[h] += acc[mt][nt][2] * a0 + acc[mt][nt][3] * a1;
            d1[h] += acc[mt][nt][2] * b0 + acc[mt][nt][3] * b1;
            if (row0 < M)
                *(__nv_bfloat162*)&Cb[(size_t)row0 * HCC + c0] =
                    __nv_bfloat162(__float2bfloat16(acc[mt][nt][0]),
                                   __float2bfloat16(acc[mt][nt][1]));
            if (row1 < M)
                *(__nv_bfloat162*)&Cb[(size_t)row1 * HCC + c0] =
                    __nv_bfloat162(__float2bfloat16(acc[mt][nt][2]),
                                   __float2bfloat16(acc[mt][nt][3]));
        }
#pragma unroll
        for (int h = 0; h < 2; h++) {
            atomicAdd(&sAs[r0l * 4 + hb0 + h], s0[h]);
            atomicAdd(&sAd[r0l * 4 + hb0 + h], d0[h]);
            atomicAdd(&sAs[(r0l + 8) * 4 + hb0 + h], s1[h]);
            atomicAdd(&sAd[(r0l + 8) * 4 + hb0 + h], d1[h]);
        }
    }
    __syncthreads();
    if (tid < 128 && bm + tid < M) {
        *(float4*)&g_as[(size_t)(bm + tid) * 4] = *(float4*)&sAs[tid * 4];
        *(float4*)&g_ad[(size_t)(bm + tid) * 4] = *(float4*)&sAd[tid * 4];
    }
}

__device__ __forceinline__ float leaky(float v) { return fmaxf(v, 0.2f * v); }

__device__ __forceinline__ void bf4_to_f(const __nv_bfloat16* p, float* f) {
    uint2 u = *(const uint2*)p;
    float2 a = __bfloat1622float2(*(const __nv_bfloat162*)&u.x);
    float2 b = __bfloat1622float2(*(const __nv_bfloat162*)&u.y);
    f[0] = a.x; f[1] = a.y; f[2] = b.x; f[3] = b.y;
}

// ---------------- single-pass online-softmax GAT aggregation ----------------
// One warp per dst node; ONE walk over the edge list (no segment-max prepass).
// Running max m, running z/acc rescaled when m grows (group-of-4 block max).
template <int SPLIT>
__global__ void k_aggregate(const __nv_bfloat16* __restrict__ hb,
                            const float* __restrict__ bias, float* __restrict__ out) {
    int node = (blockIdx.x * blockDim.x + threadIdx.x) >> 5;
    if (node >= Nn) return;
    int lane = threadIdx.x & 31;
    int head = lane >> 3;

    float ad = g_ad[node * 4 + head];
    float as_self = g_as[node * 4 + head];

    // init with self loop: m = e_self, p_self = 1
    float m = leaky(as_self + ad);
    float z = 1.f;
    float hv[4];
    bf4_to_f(&hb[(size_t)node * HCC + lane * 4], hv);
    float4 acc;
    acc.x = hv[0]; acc.y = hv[1]; acc.z = hv[2]; acc.w = hv[3];

    int beg = g_rowstart[node];
    int end = g_rowstart[node + 1];

    for (int j0 = beg; j0 < end; j0 += 32) {
        int myj = j0 + lane;
        int sj = (myj < end) ? g_csrc[myj] : 0;
        int cnt = min(32, end - j0);
        int t = 0;
        for (; t + 4 <= cnt; t += 4) {
            int s0 = __shfl_sync(0xffffffffu, sj, t);
            int s1 = __shfl_sync(0xffffffffu, sj, t + 1);
            int s2 = __shfl_sync(0xffffffffu, sj, t + 2);
            int s3 = __shfl_sync(0xffffffffu, sj, t + 3);
            float a0 = g_as[s0 * 4 + head];
            float a1 = g_as[s1 * 4 + head];
            float a2 = g_as[s2 * 4 + head];
            float a3 = g_as[s3 * 4 + head];
            float h0[4], h1[4], h2[4], h3[4];
            bf4_to_f(&hb[(size_t)s0 * HCC + lane * 4], h0);
            bf4_to_f(&hb[(size_t)s1 * HCC + lane * 4], h1);
            bf4_to_f(&hb[(size_t)s2 * HCC + lane * 4], h2);
            bf4_to_f(&hb[(size_t)s3 * HCC + lane * 4], h3);
            float e0 = leaky(a0 + ad);
            float e1 = leaky(a1 + ad);
            float e2 = leaky(a2 + ad);
            float e3 = leaky(a3 + ad);
            float em = fmaxf(fmaxf(e0, e1), fmaxf(e2, e3));
            if (em > m) {   // uniform within each 8-lane head group; cheap body
                float sc = __expf(m - em);
                z *= sc;
                acc.x *= sc; acc.y *= sc; acc.z *= sc; acc.w *= sc;
                m = em;
            }
            float p0 = __expf(e0 - m);
            float p1 = __expf(e1 - m);
            float p2 = __expf(e2 - m);
            float p3 = __expf(e3 - m);
            z += (p0 + p1) + (p2 + p3);
            acc.x = fmaf(p0, h0[0], acc.x); acc.y = fmaf(p0, h0[1], acc.y);
            acc.z = fmaf(p0, h0[2], acc.z); acc.w = fmaf(p0, h0[3], acc.w);
            acc.x = fmaf(p1, h1[0], acc.x); acc.y = fmaf(p1, h1[1], acc.y);
            acc.z = fmaf(p1, h1[2], acc.z); acc.w = fmaf(p1, h1[3], acc.w);
            acc.x = fmaf(p2, h2[0], acc.x); acc.y = fmaf(p2, h2[1], acc.y);
            acc.z = fmaf(p2, h2[2], acc.z); acc.w = fmaf(p2, h2[3], acc.w);
            acc.x = fmaf(p3, h3[0], acc.x); acc.y = fmaf(p3, h3[1], acc.y);
            acc.z = fmaf(p3, h3[2], acc.z); acc.w = fmaf(p3, h3[3], acc.w);
        }
        for (; t < cnt; t++) {
            int s = __shfl_sync(0xffffffffu, sj, t);
            float a = g_as[s * 4 + head];
            float h2[4];
            bf4_to_f(&hb[(size_t)s * HCC + lane * 4], h2);
            float e = leaky(a + ad);
            if (e > m) {
                float sc = __expf(m - e);
                z *= sc;
                acc.x *= sc; acc.y *= sc; acc.z *= sc; acc.w *= sc;
                m = e;
            }
            float p = __expf(e - m);
            z += p;
            acc.x = fmaf(p, h2[0], acc.x);
            acc.y = fmaf(p, h2[1], acc.y);
            acc.z = fmaf(p, h2[2], acc.z);
            acc.w = fmaf(p, h2[3], acc.w);
        }
    }

    float inv = 1.f / z;
    float4 b4 = *(const float4*)&bias[lane * 4];
    float4 o;
    o.x = fmaxf(fmaf(acc.x, inv, b4.x), 0.f);
    o.y = fmaxf(fmaf(acc.y, inv, b4.y), 0.f);
    o.z = fmaxf(fmaf(acc.z, inv, b4.z), 0.f);
    o.w = fmaxf(fmaf(acc.w, inv, b4.w), 0.f);

    if (SPLIT) {
        __nv_bfloat16 hx = __float2bfloat16(o.x), hy = __float2bfloat16(o.y);
        __nv_bfloat16 hz = __float2bfloat16(o.z), hw = __float2bfloat16(o.w);
        __nv_bfloat16 lx = __float2bfloat16(o.x - __bfloat162float(hx));
        __nv_bfloat16 ly = __float2bfloat16(o.y - __bfloat162float(hy));
        __nv_bfloat16 lz = __float2bfloat16(o.z - __bfloat162float(hz));
        __nv_bfloat16 lw = __float2bfloat16(o.w - __bfloat162float(hw));
        size_t base = (size_t)node * 256 + lane * 4;
        *(__nv_bfloat162*)&g_acat[base] = __nv_bfloat162(hx, hy);
        *(__nv_bfloat162*)&g_acat[base + 2] = __nv_bfloat162(hz, hw);
        *(__nv_bfloat162*)&g_acat[base + 128] = __nv_bfloat162(lx, ly);
        *(__nv_bfloat162*)&g_acat[base + 130] = __nv_bfloat162(lz, lw);
    } else {
        *(float4*)&out[(size_t)node * HCC + lane * 4] = o;
    }
}

// ---------------- pooling (count fused) ----------------
__global__ void k_pool(const float* __restrict__ hf, const int* __restrict__ batch) {
    __shared__ int sc[NG];
    int t = threadIdx.x;
    int n0 = blockIdx.x * 64;
    if (n0 >= Nn) return;
    int n1 = min(n0 + 64, Nn);
    if (t < NG) sc[t] = 0;
    __syncthreads();
    if (t < 64 && n0 + t < n1) atomicAdd(&sc[batch[n0 + t]], 1);
    __syncthreads();
    if (t < NG && sc[t]) atomicAdd(&g_cnt[t], sc[t]);

    int cur = batch[n0];
    float acc = 0.f;
    for (int n = n0; n < n1; n++) {
        int bb = batch[n];
        if (bb != cur) {
            atomicAdd(&g_pool[cur * HCC + t], acc);
            acc = 0.f;
            cur = bb;
        }
        acc += hf[(size_t)n * HCC + t];
    }
    atomicAdd(&g_pool[cur * HCC + t], acc);
}

// ---------------- classifier (self-cleans g_pool/g_cnt) ----------------
__global__ void k_classifier(const float* __restrict__ Wc1, const float* __restrict__ bc1,
                             const float* __restrict__ Wc2, const float* __restrict__ bc2,
                             float* __restrict__ out) {
    int g = blockIdx.x;
    int t = threadIdx.x;
    __shared__ float sg[HCC];
    __shared__ float sg1[CDIM];
    float inv = 1.f / (float)g_cnt[g];
    for (int c = t; c < HCC; c += 32) sg[c] = g_pool[g * HCC + c] * inv;
    __syncthreads();
    for (int c = t; c < HCC; c += 32) g_pool[g * HCC + c] = 0.f;
    if (t == 0) g_cnt[g] = 0;
    float a = bc1[t];
#pragma unroll 4
    for (int k = 0; k < HCC; k++) a = fmaf(sg[k], Wc1[k * CDIM + t], a);
    sg1[t] = a;
    __syncthreads();
    if (t < NCLS) {
        float b = bc2[t];
#pragma unroll
        for (int k = 0; k < CDIM; k++) b = fmaf(sg1[k], Wc2[k * NCLS + t], b);
        out[g * NCLS + t] = 1.f / (1.f + expf(-b));
    }
}

// ---------------- launch ----------------
extern "C" void kernel_launch(void* const* d_in, const int* in_sizes, int n_in,
                              void* d_out, int out_size) {
    const float* x    = (const float*)d_in[0];
    const int*   ei   = (const int*)d_in[1];
    const int*   batch= (const int*)d_in[2];
    const float* W1   = (const float*)d_in[3];
    const float* as1  = (const float*)d_in[4];
    const float* ad1  = (const float*)d_in[5];
    const float* b1   = (const float*)d_in[6];
    const float* W2   = (const float*)d_in[7];
    const float* as2  = (const float*)d_in[8];
    const float* ad2  = (const float*)d_in[9];
    const float* b2   = (const float*)d_in[10];
    const float* Wc1  = (const float*)d_in[11];
    const float* bc1  = (const float*)d_in[12];
    const float* Wc2  = (const float*)d_in[13];
    const float* bc2  = (const float*)d_in[14];
    float* out = (float*)d_out;

    int E = in_sizes[1] / 2;
    if (E > E_MAX) E = E_MAX;

    float* oP;
    __nv_bfloat16 *hbP, *bc1P, *bc2P;
    cudaGetSymbolAddress((void**)&oP, g_o);
    cudaGetSymbolAddress((void**)&hbP, g_hb);
    cudaGetSymbolAddress((void**)&bc1P, g_bcat);
    cudaGetSymbolAddress((void**)&bc2P, g_bcat2);

    const int smemBytes = 4 * STAGE_ELEMS * (int)sizeof(__nv_bfloat16);  // 73728

    static cudaStream_t s2 = 0;
    static cudaEvent_t evF = 0, evJ = 0;
    static int inited = 0;
    if (!inited) {
        cudaFuncSetAttribute(k_gemm_mma<F_IN>, cudaFuncAttributeMaxDynamicSharedMemorySize, smemBytes);
        cudaFuncSetAttribute(k_gemm_mma<HCC>, cudaFuncAttributeMaxDynamicSharedMemorySize, smemBytes);
        cudaStreamCreateWithFlags(&s2, cudaStreamNonBlocking);
        cudaEventCreateWithFlags(&evF, cudaEventDisableTiming);
        cudaEventCreateWithFlags(&evJ, cudaEventDisableTiming);
        inited = 1;
    }

    int tpb = 256;
    int nodeWarpBlocks = (Nn * 32 + tpb - 1) / tpb;
    int mmaBlocks = (Nn + 127) / 128;
    int edge4Blocks = ((E + 3) / 4 + tpb - 1) / tpb;
    int prepBlocks = (NA_PREP + F_IN * HCC + HCC * HCC + tpb - 1) / tpb;

    // fork: CSR build on s2 concurrent with prep+GEMM1 on main stream
    cudaEventRecord(evF, 0);
    cudaStreamWaitEvent(s2, evF, 0);
    k_deg<<<edge4Blocks, tpb, 0, s2>>>(ei, E);
    k_scanA<<<NB, SB, 0, s2>>>();
    k_scanB<<<NB, SB, 0, s2>>>();
    k_scatter<<<edge4Blocks, tpb, 0, s2>>>(ei, E);
    cudaEventRecord(evJ, s2);

    // main stream: prep + layer-1 GEMM (alpha fused)
    k_prep<<<prepBlocks, tpb>>>(x, W1, W2);
    k_gemm_mma<F_IN><<<mmaBlocks, 256, smemBytes>>>(bc1P, hbP, Nn, as1, ad1);

    // join
    cudaStreamWaitEvent(0, evJ, 0);

    // layer-1 aggregate (writes bf16 hi/lo split into g_acat)
    k_aggregate<1><<<nodeWarpBlocks, tpb>>>(hbP, b1, oP);

    // layer 2
    k_gemm_mma<HCC><<<mmaBlocks, 256, smemBytes>>>(bc2P, hbP, Nn, as2, ad2);
    k_aggregate<0><<<nodeWarpBlocks, tpb>>>(hbP, b2, oP);

    // pooling + classifier
    k_pool<<<(Nn + 63) / 64, HCC>>>(oP, batch);
    k_classifier<<<NG, 32>>>(Wc1, bc1, Wc2, bc2, out);
}